// round 11
// baseline (speedup 1.0000x reference)
#include <cuda_runtime.h>
#include <cuda_bf16.h>
#include <cstdint>
#include <cstddef>
#include <math.h>

#define BB 32
#define CC 256
#define OO 256
#define HH 56
#define WW 56
#define HWSZ 3136
#define KCH 4              // channels per stage
#define NST2 64            // stages (256/4)
#define S44 44             // 36 data + 4 zero + 4 pad floats per row
#define A_FL (128*S44)     // 5632 floats
#define B_FL (112*S44)     // 4928 floats
#define XT_FL (4*4*60)     // 960 floats: 4ch x 4rows x 60(56+pad)
#define A_BYTES (A_FL*4)   // 22528
#define B_BYTES (B_FL*4)   // 19712
#define A_CH (A_BYTES/16)  // 1408 16B chunks
#define SMEM_CONV (2*(A_BYTES+B_BYTES) + 2*XT_FL*4)   // 92160 B

// ---- scratch ----
__device__ float g_pooled[BB*CC];
__device__ float g_kern[BB*CC*4];
__device__ unsigned g_wA[(size_t)BB*2*NST2*128*S44];   // tf32 A images, ~92MB

// ---- helpers ----
__device__ __forceinline__ unsigned smem_u32(const void* p) {
    return (unsigned)__cvta_generic_to_shared((void*)p);
}
__device__ __forceinline__ void cp_async16(unsigned dst, const void* src) {
    asm volatile("cp.async.cg.shared.global [%0], [%1], 16;" :: "r"(dst), "l"(src));
}
__device__ __forceinline__ void cp_async16_z(unsigned dst, const void* src, int src_sz) {
    asm volatile("cp.async.cg.shared.global [%0], [%1], 16, %2;" :: "r"(dst), "l"(src), "r"(src_sz));
}
__device__ __forceinline__ unsigned to_tf32(float f) {
    unsigned u; asm("cvt.rna.tf32.f32 %0, %1;" : "=r"(u) : "f"(f)); return u;
}
// FFMA-only exp(x) for x in [-16, 16] (no MUFU)
__device__ __forceinline__ float fast_exp(float x) {
    float t = x * 1.4426950408889634f;          // log2(e)
    float fi = floorf(t);
    float f = t - fi;
    float p = 1.5403530393381606e-4f;
    p = fmaf(p, f, 1.3333558146428443e-3f);
    p = fmaf(p, f, 9.618129107628477e-3f);
    p = fmaf(p, f, 5.550410866482158e-2f);
    p = fmaf(p, f, 2.402265069591007e-1f);
    p = fmaf(p, f, 6.931471805599453e-1f);
    p = fmaf(p, f, 1.0f);
    int ei = (int)fi;
    return __int_as_float((ei + 127) << 23) * p;
}
#define STS128(a, r0, r1, r2, r3) asm volatile("st.shared.v4.b32 [%0], {%1,%2,%3,%4};" :: "r"(a), "r"(r0), "r"(r1), "r"(r2), "r"(r3) : "memory")
#define STG128(a, r0, r1, r2, r3) asm volatile("st.global.v4.u32 [%0], {%1,%2,%3,%4};" :: "l"(a), "r"(r0), "r"(r1), "r"(r2), "r"(r3) : "memory")

// ---------------------------------------------------------------
// Kernel 1: global average pool. one block per (b,c)
// ---------------------------------------------------------------
__global__ void pool_kernel(const float* __restrict__ x) {
    __shared__ float red[256];
    int bc = blockIdx.x;
    const float* p = x + (size_t)bc * HWSZ;
    float s = 0.f;
    for (int i = threadIdx.x; i < HWSZ; i += 256) s += p[i];
    red[threadIdx.x] = s;
    __syncthreads();
    for (int off = 128; off > 0; off >>= 1) {
        if (threadIdx.x < off) red[threadIdx.x] += red[threadIdx.x + off];
        __syncthreads();
    }
    if (threadIdx.x == 0) g_pooled[bc] = red[0] * (1.0f / (float)HWSZ);
}

// ---------------------------------------------------------------
// Kernel 2: FCs. one block per b
// ---------------------------------------------------------------
__global__ void fc_kernel(const float* __restrict__ fc1,
                          const float* __restrict__ fc2,
                          const float* __restrict__ fc2b) {
    __shared__ float ps[CC];
    __shared__ float hs[CC];
    int b = blockIdx.x, tid = threadIdx.x;
    ps[tid] = g_pooled[b*CC + tid];
    __syncthreads();
    {
        const float* r1 = fc1 + (size_t)tid * CC;
        float a = 0.f;
        #pragma unroll 8
        for (int j = 0; j < CC; j++) a = fmaf(ps[j], r1[j], a);
        hs[tid] = fmaxf(a, 0.f);
    }
    __syncthreads();
    #pragma unroll
    for (int m4 = 0; m4 < 4; m4++) {
        int m = m4*CC + tid;                        // m = c*4 + t
        const float* r2 = fc2 + (size_t)m * CC;
        float s = fc2b[m];
        #pragma unroll 8
        for (int j = 0; j < CC; j++) s = fmaf(hs[j], r2[j], s);
        g_kern[b*CC*4 + m] = s;
    }
}

// ---------------------------------------------------------------
// Kernel 3: tf32 A images, one thread per 44-float row, s-fastest order:
//   idx = img*8192 + o*64 + s  -> warp shares (img,o): cog row uniform,
//   weight reads coalesced (lane stride = 36 floats, warp = 1152 consecutive).
//   A[kk] = sigmoid(sum_t kern[b,c0+ci,t]*cog[o_g,t,r9]) * weight[o_g,c0+ci,r9]
// ---------------------------------------------------------------
__global__ void dynw_kernel(const float* __restrict__ cog,
                            const float* __restrict__ weight) {
    int idx = blockIdx.x * 256 + threadIdx.x;   // < 2^19
    int s   = idx & 63;
    int o   = (idx >> 6) & 127;
    int img = idx >> 13;
    int og = img & 1, b = img >> 1;
    int o_g = og*128 + o;
    int c0 = s*KCH;

    // cog row (warp-uniform): 9 x float4
    float cgr[36];
    {
        const float4* cgp = (const float4*)(cog + (size_t)o_g * 36);
        #pragma unroll
        for (int i = 0; i < 9; i++) {
            float4 v = cgp[i];
            cgr[i*4+0] = v.x; cgr[i*4+1] = v.y; cgr[i*4+2] = v.z; cgr[i*4+3] = v.w;
        }
    }
    // weight row (coalesced): 9 x float4 = 36 consecutive floats
    float wv[36];
    {
        const float4* wp = (const float4*)(weight + ((size_t)o_g*CC + c0)*9);
        #pragma unroll
        for (int i = 0; i < 9; i++) {
            float4 v = wp[i];
            wv[i*4+0] = v.x; wv[i*4+1] = v.y; wv[i*4+2] = v.z; wv[i*4+3] = v.w;
        }
    }
    const float4* kvp = (const float4*)(g_kern + ((size_t)b*CC + c0)*4);
    float4 kv[4];
    #pragma unroll
    for (int ci = 0; ci < 4; ci++) kv[ci] = kvp[ci];

    float dd[36];
    #pragma unroll
    for (int kk = 0; kk < 36; kk++) {
        int ci = kk/9, r9 = kk%9;               // compile-time
        float sa = kv[ci].x*cgr[r9] + kv[ci].y*cgr[9+r9]
                 + kv[ci].z*cgr[18+r9] + kv[ci].w*cgr[27+r9];
        sa = fminf(fmaxf(sa, -15.f), 15.f);
        dd[kk] = 1.0f + fast_exp(-sa);
    }
    unsigned* dst = g_wA + ((size_t)(img*NST2 + s)*128 + o) * S44;
    #pragma unroll
    for (int g = 0; g < 9; g++) {
        float d0 = dd[g*4], d1 = dd[g*4+1], d2 = dd[g*4+2], d3 = dd[g*4+3];
        float p01 = d0*d1, p23 = d2*d3;
        float P = p01 * p23;
        float rp; asm("rcp.approx.f32 %0, %1;" : "=f"(rp) : "f"(P));
        unsigned v0 = to_tf32(wv[g*4+0] * (rp*d1*p23));
        unsigned v1 = to_tf32(wv[g*4+1] * (rp*d0*p23));
        unsigned v2 = to_tf32(wv[g*4+2] * (rp*p01*d3));
        unsigned v3 = to_tf32(wv[g*4+3] * (rp*p01*d2));
        STG128(dst + g*4, v0, v1, v2, v3);
    }
    STG128(dst + 36, 0u, 0u, 0u, 0u);
    STG128(dst + 40, 0u, 0u, 0u, 0u);
}

// ---------------------------------------------------------------
// Kernel 4: TF32 mma.sync implicit-GEMM conv.
// Stage = 4 channels x 9 taps (40 k, 5 ksteps), 64 stages.
// Per stage: cp.async a 4ch x 4row x 56col x tile (16B chunks, zero-fill OOB
// rows), then 224 threads build B[112][40] in-smem (scalar LDS + STS128).
// 8 warps = 4(M) x 2(N); warp tile 32 o x 56 px; mma m16n8k8.
// ---------------------------------------------------------------
__global__ __launch_bounds__(256, 2)
void conv_kernel(const float* __restrict__ x, float* __restrict__ out) {
    extern __shared__ __align__(16) float dsm[];
    float* As = dsm;                      // [2][A_FL]
    float* Bs = dsm + 2*A_FL;             // [2][B_FL]
    float* Xt = dsm + 2*A_FL + 2*B_FL;    // [2][XT_FL]  4ch x 4row x 60

    const int tid  = threadIdx.x;
    const int lane = tid & 31;
    const int wid  = tid >> 5;
    const int warpM = wid & 3;
    const int warpN = wid >> 2;
    const int tile = blockIdx.x, og = blockIdx.y, b = blockIdx.z;
    const int h0 = tile * 2;

    const float* xb = x + (size_t)b * CC * HWSZ;
    const uint4* gA = (const uint4*)g_wA + (size_t)((b*2 + og) * NST2) * A_CH;

    // ---- xt loader mapping: 224 chunks = ci(4) x rowi(4) x c4(14) ----
    const bool lact = (tid < 224);
    const int l_ci = tid / 56;
    const int l_rw = (tid % 56) / 14;
    const int l_c4 = tid % 14;
    const int l_gh = h0 - 1 + l_rw;
    const bool l_ok = lact && (l_gh >= 0) && (l_gh < HH);
    const int l_src = l_ci*HWSZ + (l_ok ? l_gh : 0)*WW + l_c4*4;
    const unsigned l_dst = (unsigned)((l_ci*240 + l_rw*60 + l_c4*4) * 4);

    // ---- B build mapping: px = tid/2 (112), half = tid&1 covers kk half*20..+19 ----
    const int px = tid >> 1;
    const int half = tid & 1;
    const bool bact = (tid < 224);
    const int rr = px / 56, cw = px % 56;
    const bool m0 = (cw > 0);        // j3==0 valid
    const bool m2 = (cw < 55);       // j3==2 valid
    // base float index into Xt buffer: + ci*240 + (rr+i3)*60 + (cw-1+j3)
    const int xt_base = rr*60 + (cw - 1);
    const unsigned bdst = (unsigned)((px*S44 + half*20) * 4);

    float acc[2][7][4];
    #pragma unroll
    for (int m = 0; m < 2; m++)
        #pragma unroll
        for (int n = 0; n < 7; n++)
            #pragma unroll
            for (int q = 0; q < 4; q++) acc[m][n][q] = 0.f;

    const int aoff = (warpM*32 + (lane >> 2))*S44 + (lane & 3);
    const int boff = (warpN*56 + (lane >> 2))*S44 + (lane & 3);

    #define ISSUE(S, BUF)                                                        \
    {                                                                            \
        const uint4* srcA_ = gA + (size_t)(S) * A_CH;                            \
        unsigned dA_ = smem_u32(As) + (BUF)*A_BYTES;                             \
        _Pragma("unroll")                                                        \
        for (int i_ = 0; i_ < 6; i_++) {                                         \
            int ch_ = tid + i_ * 256;                                            \
            if (ch_ < A_CH) cp_async16(dA_ + ch_*16, srcA_ + ch_);               \
        }                                                                        \
        if (lact) {                                                              \
            const float* sx_ = xb + (size_t)(S) * (KCH*HWSZ) + l_src;            \
            cp_async16_z(smem_u32(Xt) + (BUF)*(XT_FL*4) + l_dst, sx_, l_ok ? 16 : 0); \
        }                                                                        \
        asm volatile("cp.async.commit_group;");                                  \
    }

    #define BUILD_B(BUF)                                                         \
    if (bact) {                                                                  \
        const float* xt_ = Xt + (BUF)*XT_FL + xt_base;                           \
        unsigned db_ = smem_u32(Bs) + (BUF)*B_BYTES + bdst;                      \
        _Pragma("unroll")                                                        \
        for (int g_ = 0; g_ < 5; g_++) {                                         \
            unsigned vv_[4];                                                     \
            _Pragma("unroll")                                                    \
            for (int u_ = 0; u_ < 4; u_++) {                                     \
                int kk_ = half*20 + g_*4 + u_;                                   \
                float v_ = 0.f;                                                  \
                if (kk_ < 36) {                                                  \
                    int ci_ = kk_/9, r9_ = kk_%9;                                \
                    int i3_ = r9_/3, j3_ = r9_%3;                                \
                    bool ok_ = (j3_ == 1) || (j3_ == 0 ? m0 : m2);               \
                    float t_ = xt_[ci_*240 + i3_*60 + j3_];                      \
                    v_ = ok_ ? t_ : 0.f;                                         \
                }                                                                \
                vv_[u_] = __float_as_uint(v_);                                   \
            }                                                                    \
            STS128(db_ + g_*16, vv_[0], vv_[1], vv_[2], vv_[3]);                 \
        }                                                                        \
    }

    // prologue
    ISSUE(0, 0);
    asm volatile("cp.async.wait_group 0;");
    __syncthreads();

    for (int s = 0; s < NST2; s++) {
        const int p = s & 1;
        if (s + 1 < NST2) ISSUE(s + 1, p ^ 1);

        BUILD_B(p);
        __syncthreads();

        const unsigned* Ap = (const unsigned*)(As + p * A_FL);
        const unsigned* Bp = (const unsigned*)(Bs + p * B_FL);
        #pragma unroll
        for (int ks = 0; ks < 5; ks++) {
            unsigned af[2][4], bf[7][2];
            #pragma unroll
            for (int m = 0; m < 2; m++) {
                const unsigned* ap = Ap + aoff + m*16*S44 + ks*8;
                af[m][0] = ap[0];
                af[m][1] = ap[8*S44];
                af[m][2] = ap[4];
                af[m][3] = ap[8*S44 + 4];
            }
            #pragma unroll
            for (int n = 0; n < 7; n++) {
                const unsigned* bp = Bp + boff + n*8*S44 + ks*8;
                bf[n][0] = bp[0];
                bf[n][1] = bp[4];
            }
            #pragma unroll
            for (int m = 0; m < 2; m++)
                #pragma unroll
                for (int n = 0; n < 7; n++)
                    asm volatile(
                        "mma.sync.aligned.m16n8k8.row.col.f32.tf32.tf32.f32 "
                        "{%0,%1,%2,%3}, {%4,%5,%6,%7}, {%8,%9}, {%0,%1,%2,%3};"
                        : "+f"(acc[m][n][0]), "+f"(acc[m][n][1]),
                          "+f"(acc[m][n][2]), "+f"(acc[m][n][3])
                        : "r"(af[m][0]), "r"(af[m][1]), "r"(af[m][2]), "r"(af[m][3]),
                          "r"(bf[n][0]), "r"(bf[n][1]));
        }

        asm volatile("cp.async.wait_group 0;");
        __syncthreads();
    }
    #undef ISSUE
    #undef BUILD_B

    // ---- epilogue: fragments -> gmem (all px of a warp share one h row) ----
    const int h = h0 + warpN;
    const int wbase = (lane & 3) * 2;
    #pragma unroll
    for (int m = 0; m < 2; m++) {
        int o = og*128 + warpM*32 + m*16 + (lane >> 2);
        float* r0 = out + ((size_t)b*OO + o)*HWSZ + h*WW;
        float* r1 = out + ((size_t)b*OO + o + 8)*HWSZ + h*WW;
        #pragma unroll
        for (int n = 0; n < 7; n++) {
            int w = n*8 + wbase;
            *(float2*)(r0 + w) = make_float2(acc[m][n][0], acc[m][n][1]);
            *(float2*)(r1 + w) = make_float2(acc[m][n][2], acc[m][n][3]);
        }
    }
}

// ---------------------------------------------------------------
extern "C" void kernel_launch(void* const* d_in, const int* in_sizes, int n_in,
                              void* d_out, int out_size) {
    const float* x      = (const float*)d_in[0];
    const float* fc1_w  = (const float*)d_in[1];
    const float* fc2_w  = (const float*)d_in[2];
    const float* fc2_b  = (const float*)d_in[3];
    const float* cog_w  = (const float*)d_in[4];
    const float* weight = (const float*)d_in[5];
    float* out = (float*)d_out;

    cudaFuncSetAttribute(conv_kernel, cudaFuncAttributeMaxDynamicSharedMemorySize, SMEM_CONV);

    pool_kernel<<<BB*CC, 256>>>(x);
    fc_kernel<<<BB, 256>>>(fc1_w, fc2_w, fc2_b);
    dynw_kernel<<<2048, 256>>>(cog_w, weight);   // 2^19 rows
    {
        dim3 grid(28, 2, BB);
        conv_kernel<<<grid, 256, SMEM_CONV>>>(x, out);
    }
}

// round 12
// speedup vs baseline: 1.8899x; 1.8899x over previous
#include <cuda_runtime.h>
#include <cuda_bf16.h>
#include <cstdint>
#include <cstddef>
#include <math.h>

#define BB 32
#define CC 256
#define OO 256
#define HH 56
#define WW 56
#define HWSZ 3136
#define KCH 4              // channels per stage
#define NST2 64            // stages (256/4)
#define S44 44             // 36 data + 4 zero + 4 pad floats per row
#define A_FL (128*S44)     // 5632 floats
#define B_FL (112*S44)     // 4928 floats
#define A_BYTES (A_FL*4)   // 22528
#define B_BYTES (B_FL*4)   // 19712
#define A_CH (A_BYTES/16)  // 1408 16B chunks
#define SMEM_CONV (2*(A_BYTES+B_BYTES))   // 84480 B

// ---- scratch ----
__device__ float g_pooled[BB*CC];
__device__ float g_kern[BB*CC*4];
__device__ unsigned g_wA[(size_t)BB*2*NST2*128*S44];   // tf32 A images, ~92MB

// ---- helpers ----
__device__ __forceinline__ unsigned smem_u32(const void* p) {
    return (unsigned)__cvta_generic_to_shared((void*)p);
}
__device__ __forceinline__ void cp_async16(unsigned dst, const void* src) {
    asm volatile("cp.async.cg.shared.global [%0], [%1], 16;" :: "r"(dst), "l"(src));
}
__device__ __forceinline__ unsigned to_tf32(float f) {
    unsigned u; asm("cvt.rna.tf32.f32 %0, %1;" : "=r"(u) : "f"(f)); return u;
}
// FFMA-only exp(x) for x in [-16, 16] (no MUFU)
__device__ __forceinline__ float fast_exp(float x) {
    float t = x * 1.4426950408889634f;          // log2(e)
    float fi = floorf(t);
    float f = t - fi;
    float p = 1.5403530393381606e-4f;
    p = fmaf(p, f, 1.3333558146428443e-3f);
    p = fmaf(p, f, 9.618129107628477e-3f);
    p = fmaf(p, f, 5.550410866482158e-2f);
    p = fmaf(p, f, 2.402265069591007e-1f);
    p = fmaf(p, f, 6.931471805599453e-1f);
    p = fmaf(p, f, 1.0f);
    int ei = (int)fi;
    return __int_as_float((ei + 127) << 23) * p;
}
#define STS128(a, r0, r1, r2, r3) asm volatile("st.shared.v4.b32 [%0], {%1,%2,%3,%4};" :: "r"(a), "r"(r0), "r"(r1), "r"(r2), "r"(r3) : "memory")
#define STG128(a, r0, r1, r2, r3) asm volatile("st.global.v4.u32 [%0], {%1,%2,%3,%4};" :: "l"(a), "r"(r0), "r"(r1), "r"(r2), "r"(r3) : "memory")

// ---------------------------------------------------------------
// Kernel 1: global average pool. one block per (b,c)
// ---------------------------------------------------------------
__global__ void pool_kernel(const float* __restrict__ x) {
    __shared__ float red[256];
    int bc = blockIdx.x;
    const float* p = x + (size_t)bc * HWSZ;
    float s = 0.f;
    for (int i = threadIdx.x; i < HWSZ; i += 256) s += p[i];
    red[threadIdx.x] = s;
    __syncthreads();
    for (int off = 128; off > 0; off >>= 1) {
        if (threadIdx.x < off) red[threadIdx.x] += red[threadIdx.x + off];
        __syncthreads();
    }
    if (threadIdx.x == 0) g_pooled[bc] = red[0] * (1.0f / (float)HWSZ);
}

// ---------------------------------------------------------------
// Kernel 2: FCs. one block per b
// ---------------------------------------------------------------
__global__ void fc_kernel(const float* __restrict__ fc1,
                          const float* __restrict__ fc2,
                          const float* __restrict__ fc2b) {
    __shared__ float ps[CC];
    __shared__ float hs[CC];
    int b = blockIdx.x, tid = threadIdx.x;
    ps[tid] = g_pooled[b*CC + tid];
    __syncthreads();
    {
        const float* r1 = fc1 + (size_t)tid * CC;
        float a = 0.f;
        #pragma unroll 8
        for (int j = 0; j < CC; j++) a = fmaf(ps[j], r1[j], a);
        hs[tid] = fmaxf(a, 0.f);
    }
    __syncthreads();
    #pragma unroll
    for (int m4 = 0; m4 < 4; m4++) {
        int m = m4*CC + tid;                        // m = c*4 + t
        const float* r2 = fc2 + (size_t)m * CC;
        float s = fc2b[m];
        #pragma unroll 8
        for (int j = 0; j < CC; j++) s = fmaf(hs[j], r2[j], s);
        g_kern[b*CC*4 + m] = s;
    }
}

// ---------------------------------------------------------------
// Kernel 3: tf32 A images. One thread per data quad (9 per 44-float row).
//   row = img*8192 + s*128 + o  (matches conv's linear A read order)
//   A[kk] = sigmoid(sum_t kern[b,c0+ci,t]*cog[o_g,t,r9]) * weight[o_g,c0+ci,r9]
//   floats 36..39 zeroed (read by kstep 4); 40..43 never read.
// ---------------------------------------------------------------
__global__ void dynw_kernel(const float* __restrict__ cog,
                            const float* __restrict__ weight) {
    int idx = blockIdx.x * 256 + threadIdx.x;   // < 2^19 * 9
    int row = idx / 9;
    int g   = idx - row * 9;
    int o   = row & 127;
    int s   = (row >> 7) & 63;
    int img = row >> 13;
    int og = img & 1, b = img >> 1;
    int o_g = og*128 + o;
    int c0 = s*KCH;

    const float* cg = cog + (size_t)o_g * 36;
    float4 wq = *(const float4*)(weight + ((size_t)o_g*CC + c0)*9 + g*4);
    float wv[4] = {wq.x, wq.y, wq.z, wq.w};
    float d[4];
    #pragma unroll
    for (int u = 0; u < 4; u++) {
        int kk = g*4 + u;
        int ci = kk/9, r9 = kk - ci*9;
        const float4 kv = *(const float4*)(g_kern + ((size_t)b*CC + c0 + ci)*4);
        float sa = kv.x*cg[r9] + kv.y*cg[9+r9] + kv.z*cg[18+r9] + kv.w*cg[27+r9];
        sa = fminf(fmaxf(sa, -15.f), 15.f);
        d[u] = 1.0f + fast_exp(-sa);
    }
    float p01 = d[0]*d[1], p23 = d[2]*d[3];
    float P = p01 * p23;
    float rp; asm("rcp.approx.f32 %0, %1;" : "=f"(rp) : "f"(P));
    unsigned v0 = to_tf32(wv[0] * (rp*d[1]*p23));
    unsigned v1 = to_tf32(wv[1] * (rp*d[0]*p23));
    unsigned v2 = to_tf32(wv[2] * (rp*p01*d[3]));
    unsigned v3 = to_tf32(wv[3] * (rp*p01*d[2]));
    unsigned* dst = g_wA + (size_t)row * S44 + g*4;
    STG128(dst, v0, v1, v2, v3);
    if (g == 0) {   // zero the kstep-4 tail (floats 36..39)
        STG128(g_wA + (size_t)row * S44 + 36, 0u, 0u, 0u, 0u);
    }
}

// ---------------------------------------------------------------
// Kernel 4: TF32 mma.sync implicit-GEMM conv.
// Stage = 4 channels x 9 taps (40 k, 5 ksteps), 64 stages.
// B feed: coalesced predicated LDG prefetch (compile-time offsets via
// half-branch) overlapped with MMA; STS128 commit after MMA (raw fp32
// bits -> HMMA tf32 truncation).
// 8 warps = 4(M) x 2(N); warp tile 32 o x 56 px; mma m16n8k8.
// ---------------------------------------------------------------
__global__ __launch_bounds__(256, 2)
void conv_kernel(const float* __restrict__ x, float* __restrict__ out) {
    extern __shared__ __align__(16) float dsm[];
    float* As = dsm;                      // [2][A_FL]
    float* Bs = dsm + 2*A_FL;             // [2][B_FL]

    const int tid  = threadIdx.x;
    const int lane = tid & 31;
    const int wid  = tid >> 5;
    const int warpM = wid & 3;
    const int warpN = wid >> 2;
    const int tile = blockIdx.x, og = blockIdx.y, b = blockIdx.z;
    const int h0 = tile * 2;

    const float* xb = x + (size_t)b * CC * HWSZ;
    const uint4* gA = (const uint4*)g_wA + (size_t)((b*2 + og) * NST2) * A_CH;

    // ---- B feed mapping: half = tid/112 (kk base = half*20), px = tid%112 ----
    const int half = tid / 112;          // 0,1 active; 2 inactive
    const int px   = tid - half*112;
    const bool bact = (tid < 224);
    const int rr = px / 56, cw = px % 56;
    const int ghb = h0 + rr - 1, gwb = cw - 1;
    const int cbase = ghb*WW + gwb;

    unsigned vmask = 0;
    {
        #pragma unroll
        for (int u = 0; u < 20; u++) {
            int kk = half*20 + u;
            int ci = kk/9, r9 = kk - ci*9;
            int i3 = r9/3, j3 = r9 - i3*3;
            int gh = ghb + i3, gw = gwb + j3;
            bool ok = bact && (kk < 36) && (gh >= 0) && (gh < HH) && (gw >= 0) && (gw < WW);
            vmask |= (ok ? 1u : 0u) << u;
        }
    }
    const unsigned bdst0 = (unsigned)((px*S44 + half*20) * 4);   // byte offset in B buf

    float acc[2][7][4];
    #pragma unroll
    for (int m = 0; m < 2; m++)
        #pragma unroll
        for (int n = 0; n < 7; n++)
            #pragma unroll
            for (int q = 0; q < 4; q++) acc[m][n][q] = 0.f;

    const int aoff = (warpM*32 + (lane >> 2))*S44 + (lane & 3);
    const int boff = (warpN*56 + (lane >> 2))*S44 + (lane & 3);

    // compile-time offset prefetch: KKB is a literal 0 or 20
    #define PF_B(XS, KKB)                                                        \
        _Pragma("unroll")                                                        \
        for (int u_ = 0; u_ < 20; u_++) {                                        \
            const int kk_ = (KKB) + u_;                                          \
            const int off_ = (kk_/9)*HWSZ + (((kk_%9))/3)*WW + ((kk_%9)%3);      \
            vreg[u_] = ((vmask >> u_) & 1) ? __ldg((XS) + cbase + off_) : 0.f;   \
        }

    #define ISSUE_A(S, BUF)                                                      \
    {                                                                            \
        const uint4* srcA_ = gA + (size_t)(S) * A_CH;                            \
        unsigned dA_ = smem_u32(As) + (BUF)*A_BYTES;                             \
        _Pragma("unroll")                                                        \
        for (int i_ = 0; i_ < 6; i_++) {                                         \
            int ch_ = tid + i_ * 256;                                            \
            if (ch_ < A_CH) cp_async16(dA_ + ch_*16, srcA_ + ch_);               \
        }                                                                        \
        asm volatile("cp.async.commit_group;");                                  \
    }

    #define COMMIT_B(BUF)                                                        \
    if (bact) {                                                                  \
        unsigned db_ = smem_u32(Bs) + (BUF)*B_BYTES + bdst0;                     \
        _Pragma("unroll")                                                        \
        for (int g_ = 0; g_ < 5; g_++)                                           \
            STS128(db_ + g_*16,                                                  \
                   __float_as_uint(vreg[g_*4+0]), __float_as_uint(vreg[g_*4+1]), \
                   __float_as_uint(vreg[g_*4+2]), __float_as_uint(vreg[g_*4+3]));\
    }
    // note: half1 writes floats 20..39; vreg[16..19]=0 by vmask -> zeros land
    // in 36..39 (the kstep-4 tail) every stage. half0 writes floats 0..19.

    // ---- zero pad floats 40..43 once in both buffers (never read, but keep clean) ----
    if (tid < 112) {
        STS128(smem_u32(Bs + 0*B_FL + tid*S44 + 40), 0u, 0u, 0u, 0u);
        STS128(smem_u32(Bs + 1*B_FL + tid*S44 + 40), 0u, 0u, 0u, 0u);
    }

    // ---- prologue: stage 0 ----
    {
        float vreg[20];
        ISSUE_A(0, 0);
        if (bact) {
            const float* xs = xb;
            if (half == 0) { PF_B(xs, 0) } else { PF_B(xs, 20) }
        }
        COMMIT_B(0);
        asm volatile("cp.async.wait_group 0;");
        __syncthreads();
    }

    for (int s = 0; s < NST2; s++) {
        const int p = s & 1;

        // ---- issue next-stage A + prefetch next-stage B into registers ----
        float vreg[20];
        if (s + 1 < NST2) {
            ISSUE_A(s + 1, p ^ 1);
            if (bact) {
                const float* xs = xb + (size_t)(s + 1) * (KCH*HWSZ);
                if (half == 0) { PF_B(xs, 0) } else { PF_B(xs, 20) }
            }
        }

        // ---- MMA on stage s ----
        const unsigned* Ap = (const unsigned*)(As + p * A_FL);
        const unsigned* Bp = (const unsigned*)(Bs + p * B_FL);
        #pragma unroll
        for (int ks = 0; ks < 5; ks++) {
            unsigned af[2][4], bf[7][2];
            #pragma unroll
            for (int m = 0; m < 2; m++) {
                const unsigned* ap = Ap + aoff + m*16*S44 + ks*8;
                af[m][0] = ap[0];
                af[m][1] = ap[8*S44];
                af[m][2] = ap[4];
                af[m][3] = ap[8*S44 + 4];
            }
            #pragma unroll
            for (int n = 0; n < 7; n++) {
                const unsigned* bp = Bp + boff + n*8*S44 + ks*8;
                bf[n][0] = bp[0];
                bf[n][1] = bp[4];
            }
            #pragma unroll
            for (int m = 0; m < 2; m++)
                #pragma unroll
                for (int n = 0; n < 7; n++)
                    asm volatile(
                        "mma.sync.aligned.m16n8k8.row.col.f32.tf32.tf32.f32 "
                        "{%0,%1,%2,%3}, {%4,%5,%6,%7}, {%8,%9}, {%0,%1,%2,%3};"
                        : "+f"(acc[m][n][0]), "+f"(acc[m][n][1]),
                          "+f"(acc[m][n][2]), "+f"(acc[m][n][3])
                        : "r"(af[m][0]), "r"(af[m][1]), "r"(af[m][2]), "r"(af[m][3]),
                          "r"(bf[n][0]), "r"(bf[n][1]));
        }

        // ---- commit prefetched B to the other buffer ----
        if (s + 1 < NST2) COMMIT_B(p ^ 1);

        asm volatile("cp.async.wait_group 0;");
        __syncthreads();
    }
    #undef ISSUE_A
    #undef COMMIT_B
    #undef PF_B

    // ---- epilogue: fragments -> gmem (all px of a warp share one h row) ----
    const int h = h0 + warpN;
    const int wbase = (lane & 3) * 2;
    #pragma unroll
    for (int m = 0; m < 2; m++) {
        int o = og*128 + warpM*32 + m*16 + (lane >> 2);
        float* r0 = out + ((size_t)b*OO + o)*HWSZ + h*WW;
        float* r1 = out + ((size_t)b*OO + o + 8)*HWSZ + h*WW;
        #pragma unroll
        for (int n = 0; n < 7; n++) {
            int w = n*8 + wbase;
            *(float2*)(r0 + w) = make_float2(acc[m][n][0], acc[m][n][1]);
            *(float2*)(r1 + w) = make_float2(acc[m][n][2], acc[m][n][3]);
        }
    }
}

// ---------------------------------------------------------------
extern "C" void kernel_launch(void* const* d_in, const int* in_sizes, int n_in,
                              void* d_out, int out_size) {
    const float* x      = (const float*)d_in[0];
    const float* fc1_w  = (const float*)d_in[1];
    const float* fc2_w  = (const float*)d_in[2];
    const float* fc2_b  = (const float*)d_in[3];
    const float* cog_w  = (const float*)d_in[4];
    const float* weight = (const float*)d_in[5];
    float* out = (float*)d_out;

    cudaFuncSetAttribute(conv_kernel, cudaFuncAttributeMaxDynamicSharedMemorySize, SMEM_CONV);

    pool_kernel<<<BB*CC, 256>>>(x);
    fc_kernel<<<BB, 256>>>(fc1_w, fc2_w, fc2_b);
    dynw_kernel<<<18432, 256>>>(cog_w, weight);   // 2^19 rows x 9 quads
    {
        dim3 grid(28, 2, BB);
        conv_kernel<<<grid, 256, SMEM_CONV>>>(x, out);
    }
}

// round 13
// speedup vs baseline: 2.9045x; 1.5368x over previous
#include <cuda_runtime.h>
#include <cuda_bf16.h>
#include <cuda_fp16.h>
#include <cstdint>
#include <cstddef>
#include <math.h>

#define BB 32
#define CC 256
#define OO 256
#define HH 56
#define WW 56
#define HWSZ 3136
#define KCH 4              // channels per stage
#define NST2 64            // stages (256/4)
#define SWD 28             // 32b words per row: 24 data words (48 fp16: 36 real+12 zero) + 4 pad
#define A_WORDS (128*SWD)  // 3584
#define B_WORDS (112*SWD)  // 3136
#define A_BYTES (A_WORDS*4)   // 14336
#define B_BYTES (B_WORDS*4)   // 12544
#define A_CH (A_BYTES/16)     // 896 16B chunks
#define SMEM_CONV (2*(A_BYTES+B_BYTES))   // 53760 B

// ---- scratch ----
__device__ float g_pooled[BB*CC];
__device__ float g_kern[BB*CC*4];
__device__ unsigned g_wA[(size_t)BB*2*NST2*128*SWD];   // fp16 A images, ~58.7MB

// ---- helpers ----
__device__ __forceinline__ unsigned smem_u32(const void* p) {
    return (unsigned)__cvta_generic_to_shared((void*)p);
}
__device__ __forceinline__ void cp_async16(unsigned dst, const void* src) {
    asm volatile("cp.async.cg.shared.global [%0], [%1], 16;" :: "r"(dst), "l"(src));
}
__device__ __forceinline__ unsigned h2bits(float lo, float hi) {
    __half2 h = __floats2half2_rn(lo, hi);
    return *(unsigned*)&h;
}
// FFMA-only exp(x) for x in [-16, 16] (no MUFU)
__device__ __forceinline__ float fast_exp(float x) {
    float t = x * 1.4426950408889634f;          // log2(e)
    float fi = floorf(t);
    float f = t - fi;
    float p = 1.5403530393381606e-4f;
    p = fmaf(p, f, 1.3333558146428443e-3f);
    p = fmaf(p, f, 9.618129107628477e-3f);
    p = fmaf(p, f, 5.550410866482158e-2f);
    p = fmaf(p, f, 2.402265069591007e-1f);
    p = fmaf(p, f, 6.931471805599453e-1f);
    p = fmaf(p, f, 1.0f);
    int ei = (int)fi;
    return __int_as_float((ei + 127) << 23) * p;
}
#define STS128(a, r0, r1, r2, r3) asm volatile("st.shared.v4.b32 [%0], {%1,%2,%3,%4};" :: "r"(a), "r"(r0), "r"(r1), "r"(r2), "r"(r3) : "memory")
#define STS64(a, r0, r1) asm volatile("st.shared.v2.b32 [%0], {%1,%2};" :: "r"(a), "r"(r0), "r"(r1) : "memory")

// ---------------------------------------------------------------
// Kernel 1: global average pool. one block per (b,c)
// ---------------------------------------------------------------
__global__ void pool_kernel(const float* __restrict__ x) {
    __shared__ float red[256];
    int bc = blockIdx.x;
    const float4* p = (const float4*)(x + (size_t)bc * HWSZ);
    float s = 0.f;
    for (int i = threadIdx.x; i < HWSZ/4; i += 256) {
        float4 v = p[i];
        s += (v.x + v.y) + (v.z + v.w);
    }
    red[threadIdx.x] = s;
    __syncthreads();
    for (int off = 128; off > 0; off >>= 1) {
        if (threadIdx.x < off) red[threadIdx.x] += red[threadIdx.x + off];
        __syncthreads();
    }
    if (threadIdx.x == 0) g_pooled[bc] = red[0] * (1.0f / (float)HWSZ);
}

// ---------------------------------------------------------------
// Kernel 2: FCs. one block per b (float4 loads)
// ---------------------------------------------------------------
__global__ void fc_kernel(const float* __restrict__ fc1,
                          const float* __restrict__ fc2,
                          const float* __restrict__ fc2b) {
    __shared__ float ps[CC];
    __shared__ float hs[CC];
    int b = blockIdx.x, tid = threadIdx.x;
    ps[tid] = g_pooled[b*CC + tid];
    __syncthreads();
    {
        const float4* r1 = (const float4*)(fc1 + (size_t)tid * CC);
        float a = 0.f;
        #pragma unroll 8
        for (int j = 0; j < CC/4; j++) {
            float4 v = r1[j];
            a += ps[4*j]*v.x + ps[4*j+1]*v.y + ps[4*j+2]*v.z + ps[4*j+3]*v.w;
        }
        hs[tid] = fmaxf(a, 0.f);
    }
    __syncthreads();
    #pragma unroll
    for (int m4 = 0; m4 < 4; m4++) {
        int m = m4*CC + tid;                        // m = c*4 + t
        const float4* r2 = (const float4*)(fc2 + (size_t)m * CC);
        float s = fc2b[m];
        #pragma unroll 8
        for (int j = 0; j < CC/4; j++) {
            float4 v = r2[j];
            s += hs[4*j]*v.x + hs[4*j+1]*v.y + hs[4*j+2]*v.z + hs[4*j+3]*v.w;
        }
        g_kern[b*CC*4 + m] = s;
    }
}

// ---------------------------------------------------------------
// Kernel 3: fp16 A images. One thread per data quad (9 per row).
//   row = img*8192 + s*128 + o; word w holds kk {2w, 2w+1} as half2.
//   A[kk] = sigmoid(sum_t kern[b,c0+ci,t]*cog[o_g,t,r9]) * weight[o_g,c0+ci,r9]
//   words 18..23 (kk 36..47) zeroed; 24..27 pad never read.
// ---------------------------------------------------------------
__global__ void dynw_kernel(const float* __restrict__ cog,
                            const float* __restrict__ weight) {
    int idx = blockIdx.x * 256 + threadIdx.x;   // < 2^19 * 9
    int row = idx / 9;
    int g   = idx - row * 9;
    int o   = row & 127;
    int s   = (row >> 7) & 63;
    int img = row >> 13;
    int og = img & 1, b = img >> 1;
    int o_g = og*128 + o;
    int c0 = s*KCH;

    const float* cg = cog + (size_t)o_g * 36;
    float4 wq = *(const float4*)(weight + ((size_t)o_g*CC + c0)*9 + g*4);
    float wv[4] = {wq.x, wq.y, wq.z, wq.w};
    float d[4];
    #pragma unroll
    for (int u = 0; u < 4; u++) {
        int kk = g*4 + u;
        int ci = kk/9, r9 = kk - ci*9;
        const float4 kv = *(const float4*)(g_kern + ((size_t)b*CC + c0 + ci)*4);
        float sa = kv.x*cg[r9] + kv.y*cg[9+r9] + kv.z*cg[18+r9] + kv.w*cg[27+r9];
        sa = fminf(fmaxf(sa, -15.f), 15.f);
        d[u] = 1.0f + fast_exp(-sa);
    }
    float p01 = d[0]*d[1], p23 = d[2]*d[3];
    float P = p01 * p23;
    float rp; asm("rcp.approx.f32 %0, %1;" : "=f"(rp) : "f"(P));
    float v0 = wv[0] * (rp*d[1]*p23);
    float v1 = wv[1] * (rp*d[0]*p23);
    float v2 = wv[2] * (rp*p01*d[3]);
    float v3 = wv[3] * (rp*p01*d[2]);
    unsigned* dst = g_wA + (size_t)row * SWD + g*2;
    *(uint2*)dst = make_uint2(h2bits(v0, v1), h2bits(v2, v3));
    if (g < 3) {   // zero words 18..23 (kk 36..47, read by kstep 2)
        *(uint2*)(g_wA + (size_t)row * SWD + 18 + g*2) = make_uint2(0u, 0u);
    }
}

// ---------------------------------------------------------------
// Kernel 4: FP16 mma.sync implicit-GEMM conv.
// Stage = 4 channels x 9 taps -> 48 fp16 k (36 real), 3 ksteps of 16. 64 stages.
// B feed: coalesced predicated fp32 LDG prefetch (compile-time offsets)
// overlapped with MMA; half2 pack + STS commit after MMA.
// 8 warps = 4(M) x 2(N); warp tile 32 o x 56 px; mma m16n8k16.f16.
// ---------------------------------------------------------------
__global__ __launch_bounds__(256, 2)
void conv_kernel(const float* __restrict__ x, float* __restrict__ out) {
    extern __shared__ __align__(16) float dsm[];
    unsigned* As = (unsigned*)dsm;             // [2][A_WORDS]
    unsigned* Bs = (unsigned*)dsm + 2*A_WORDS; // [2][B_WORDS]

    const int tid  = threadIdx.x;
    const int lane = tid & 31;
    const int wid  = tid >> 5;
    const int warpM = wid & 3;
    const int warpN = wid >> 2;
    const int tile = blockIdx.x, og = blockIdx.y, b = blockIdx.z;
    const int h0 = tile * 2;

    const float* xb = x + (size_t)b * CC * HWSZ;
    const uint4* gA = (const uint4*)g_wA + (size_t)((b*2 + og) * NST2) * A_CH;

    // ---- B feed mapping: half = tid/112 (kk base = half*20), px = tid%112 ----
    const int half = tid / 112;          // 0,1 active; 2 inactive
    const int px   = tid - half*112;
    const bool bact = (tid < 224);
    const int rr = px / 56, cw = px % 56;
    const int ghb = h0 + rr - 1, gwb = cw - 1;
    const int cbase = ghb*WW + gwb;

    unsigned vmask = 0;
    {
        #pragma unroll
        for (int u = 0; u < 20; u++) {
            int kk = half*20 + u;
            int ci = kk/9, r9 = kk - ci*9;
            int i3 = r9/3, j3 = r9 - i3*3;
            int gh = ghb + i3, gw = gwb + j3;
            bool ok = bact && (kk < 36) && (gh >= 0) && (gh < HH) && (gw >= 0) && (gw < WW);
            vmask |= (ok ? 1u : 0u) << u;
        }
    }

    float acc[2][7][4];
    #pragma unroll
    for (int m = 0; m < 2; m++)
        #pragma unroll
        for (int n = 0; n < 7; n++)
            #pragma unroll
            for (int q = 0; q < 4; q++) acc[m][n][q] = 0.f;

    const int aoff = (warpM*32 + (lane >> 2))*SWD + (lane & 3);
    const int boff = (warpN*56 + (lane >> 2))*SWD + (lane & 3);

    // compile-time offset prefetch: KKB is a literal 0 or 20
    #define PF_B(XS, KKB)                                                        \
        _Pragma("unroll")                                                        \
        for (int u_ = 0; u_ < 20; u_++) {                                        \
            const int kk_ = (KKB) + u_;                                          \
            const int off_ = (kk_/9)*HWSZ + (((kk_%9))/3)*WW + ((kk_%9)%3);      \
            vreg[u_] = ((vmask >> u_) & 1) ? __ldg((XS) + cbase + off_) : 0.f;   \
        }

    #define ISSUE_A(S, BUF)                                                      \
    {                                                                            \
        const uint4* srcA_ = gA + (size_t)(S) * A_CH;                            \
        unsigned dA_ = smem_u32(As) + (BUF)*A_BYTES;                             \
        _Pragma("unroll")                                                        \
        for (int i_ = 0; i_ < 4; i_++) {                                         \
            int ch_ = tid + i_ * 256;                                            \
            if (ch_ < A_CH) cp_async16(dA_ + ch_*16, srcA_ + ch_);               \
        }                                                                        \
        asm volatile("cp.async.commit_group;");                                  \
    }

    // pack 20 fp32 -> 10 half2 words; half0 -> bytes 0..39, half1 -> 40..79 of row
    #define COMMIT_B(BUF)                                                        \
    if (bact) {                                                                  \
        unsigned w_[10];                                                         \
        _Pragma("unroll")                                                        \
        for (int i_ = 0; i_ < 10; i_++)                                          \
            w_[i_] = h2bits(vreg[2*i_], vreg[2*i_+1]);                           \
        unsigned db_ = smem_u32(Bs) + (BUF)*B_BYTES + px*112;                    \
        if (half == 0) {                                                         \
            STS128(db_ + 0,  w_[0], w_[1], w_[2], w_[3]);                        \
            STS128(db_ + 16, w_[4], w_[5], w_[6], w_[7]);                        \
            STS64 (db_ + 32, w_[8], w_[9]);                                      \
        } else {                                                                 \
            STS64 (db_ + 40, w_[0], w_[1]);                                      \
            STS128(db_ + 48, w_[2], w_[3], w_[4], w_[5]);                        \
            STS128(db_ + 64, w_[6], w_[7], w_[8], w_[9]);                        \
        }                                                                        \
    }

    // ---- zero B words 20..23 (kk 40..47, read by kstep 2) once, both buffers ----
    if (tid < 112) {
        STS128(smem_u32(Bs) + 0*B_BYTES + tid*112 + 80, 0u, 0u, 0u, 0u);
        STS128(smem_u32(Bs) + 1*B_BYTES + tid*112 + 80, 0u, 0u, 0u, 0u);
    }

    // ---- prologue: stage 0 ----
    {
        float vreg[20];
        ISSUE_A(0, 0);
        if (bact) {
            const float* xs = xb;
            if (half == 0) { PF_B(xs, 0) } else { PF_B(xs, 20) }
        }
        COMMIT_B(0);
        asm volatile("cp.async.wait_group 0;");
        __syncthreads();
    }

    for (int s = 0; s < NST2; s++) {
        const int p = s & 1;

        // ---- issue next-stage A + prefetch next-stage B into registers ----
        float vreg[20];
        if (s + 1 < NST2) {
            ISSUE_A(s + 1, p ^ 1);
            if (bact) {
                const float* xs = xb + (size_t)(s + 1) * (KCH*HWSZ);
                if (half == 0) { PF_B(xs, 0) } else { PF_B(xs, 20) }
            }
        }

        // ---- MMA on stage s: 3 ksteps of K=16 ----
        const unsigned* Ap = As + p * A_WORDS;
        const unsigned* Bp = Bs + p * B_WORDS;
        #pragma unroll
        for (int ks = 0; ks < 3; ks++) {
            unsigned af[2][4], bf[7][2];
            #pragma unroll
            for (int m = 0; m < 2; m++) {
                const unsigned* ap = Ap + aoff + m*(16*SWD) + ks*8;
                af[m][0] = ap[0];
                af[m][1] = ap[8*SWD];
                af[m][2] = ap[4];
                af[m][3] = ap[8*SWD + 4];
            }
            #pragma unroll
            for (int n = 0; n < 7; n++) {
                const unsigned* bp = Bp + boff + n*(8*SWD) + ks*8;
                bf[n][0] = bp[0];
                bf[n][1] = bp[4];
            }
            #pragma unroll
            for (int m = 0; m < 2; m++)
                #pragma unroll
                for (int n = 0; n < 7; n++)
                    asm volatile(
                        "mma.sync.aligned.m16n8k16.row.col.f32.f16.f16.f32 "
                        "{%0,%1,%2,%3}, {%4,%5,%6,%7}, {%8,%9}, {%0,%1,%2,%3};"
                        : "+f"(acc[m][n][0]), "+f"(acc[m][n][1]),
                          "+f"(acc[m][n][2]), "+f"(acc[m][n][3])
                        : "r"(af[m][0]), "r"(af[m][1]), "r"(af[m][2]), "r"(af[m][3]),
                          "r"(bf[n][0]), "r"(bf[n][1]));
        }

        // ---- commit prefetched B to the other buffer ----
        if (s + 1 < NST2) COMMIT_B(p ^ 1);

        asm volatile("cp.async.wait_group 0;");
        __syncthreads();
    }
    #undef ISSUE_A
    #undef COMMIT_B
    #undef PF_B

    // ---- epilogue: fragments -> gmem (all px of a warp share one h row) ----
    const int h = h0 + warpN;
    const int wbase = (lane & 3) * 2;
    #pragma unroll
    for (int m = 0; m < 2; m++) {
        int o = og*128 + warpM*32 + m*16 + (lane >> 2);
        float* r0 = out + ((size_t)b*OO + o)*HWSZ + h*WW;
        float* r1 = out + ((size_t)b*OO + o + 8)*HWSZ + h*WW;
        #pragma unroll
        for (int n = 0; n < 7; n++) {
            int w = n*8 + wbase;
            *(float2*)(r0 + w) = make_float2(acc[m][n][0], acc[m][n][1]);
            *(float2*)(r1 + w) = make_float2(acc[m][n][2], acc[m][n][3]);
        }
    }
}

// ---------------------------------------------------------------
extern "C" void kernel_launch(void* const* d_in, const int* in_sizes, int n_in,
                              void* d_out, int out_size) {
    const float* x      = (const float*)d_in[0];
    const float* fc1_w  = (const float*)d_in[1];
    const float* fc2_w  = (const float*)d_in[2];
    const float* fc2_b  = (const float*)d_in[3];
    const float* cog_w  = (const float*)d_in[4];
    const float* weight = (const float*)d_in[5];
    float* out = (float*)d_out;

    cudaFuncSetAttribute(conv_kernel, cudaFuncAttributeMaxDynamicSharedMemorySize, SMEM_CONV);

    pool_kernel<<<BB*CC, 256>>>(x);
    fc_kernel<<<BB, 256>>>(fc1_w, fc2_w, fc2_b);
    dynw_kernel<<<18432, 256>>>(cog_w, weight);   // 2^19 rows x 9 quads
    {
        dim3 grid(28, 2, BB);
        conv_kernel<<<grid, 256, SMEM_CONV>>>(x, out);
    }
}

// round 14
// speedup vs baseline: 3.1975x; 1.1009x over previous
#include <cuda_runtime.h>
#include <cuda_bf16.h>
#include <cuda_fp16.h>
#include <cstdint>
#include <cstddef>
#include <math.h>

#define BB 32
#define CC 256
#define OO 256
#define HH 56
#define WW 56
#define HWSZ 3136
#define KCH 4              // channels per stage
#define NST2 64            // stages (256/4)
#define SWD 28             // 32b words per row: 24 data words (48 fp16) + 4 pad
#define A_WORDS (128*SWD)  // 3584
#define B_WORDS (112*SWD)  // 3136
#define A_BYTES (A_WORDS*4)   // 14336
#define B_BYTES (B_WORDS*4)   // 12544
#define A_CH (A_BYTES/16)     // 896 16B chunks
#define SMEM_CONV (3*A_BYTES + 2*B_BYTES)   // 68096 B

// ---- scratch ----
__device__ float g_pooled[BB*CC];
__device__ float g_kern[BB*CC*4];
__device__ unsigned g_wA[(size_t)BB*2*NST2*128*SWD];   // fp16 A images, ~58.7MB

// ---- helpers ----
__device__ __forceinline__ unsigned smem_u32(const void* p) {
    return (unsigned)__cvta_generic_to_shared((void*)p);
}
__device__ __forceinline__ void cp_async16(unsigned dst, const void* src) {
    asm volatile("cp.async.cg.shared.global [%0], [%1], 16;" :: "r"(dst), "l"(src));
}
__device__ __forceinline__ unsigned h2bits(float lo, float hi) {
    __half2 h = __floats2half2_rn(lo, hi);
    return *(unsigned*)&h;
}
// FFMA-only exp(x) for x in [-16, 16] (no MUFU)
__device__ __forceinline__ float fast_exp(float x) {
    float t = x * 1.4426950408889634f;          // log2(e)
    float fi = floorf(t);
    float f = t - fi;
    float p = 1.5403530393381606e-4f;
    p = fmaf(p, f, 1.3333558146428443e-3f);
    p = fmaf(p, f, 9.618129107628477e-3f);
    p = fmaf(p, f, 5.550410866482158e-2f);
    p = fmaf(p, f, 2.402265069591007e-1f);
    p = fmaf(p, f, 6.931471805599453e-1f);
    p = fmaf(p, f, 1.0f);
    int ei = (int)fi;
    return __int_as_float((ei + 127) << 23) * p;
}
#define STS128(a, r0, r1, r2, r3) asm volatile("st.shared.v4.b32 [%0], {%1,%2,%3,%4};" :: "r"(a), "r"(r0), "r"(r1), "r"(r2), "r"(r3) : "memory")
#define STS64(a, r0, r1) asm volatile("st.shared.v2.b32 [%0], {%1,%2};" :: "r"(a), "r"(r0), "r"(r1) : "memory")
#define LDSM4(r0, r1, r2, r3, addr) asm volatile( \
    "ldmatrix.sync.aligned.m8n8.x4.shared.b16 {%0,%1,%2,%3}, [%4];" \
    : "=r"(r0), "=r"(r1), "=r"(r2), "=r"(r3) : "r"(addr))
#define LDSM2(r0, r1, addr) asm volatile( \
    "ldmatrix.sync.aligned.m8n8.x2.shared.b16 {%0,%1}, [%2];" \
    : "=r"(r0), "=r"(r1) : "r"(addr))

// ---------------------------------------------------------------
// Kernel 1: global average pool. one block per (b,c)
// ---------------------------------------------------------------
__global__ void pool_kernel(const float* __restrict__ x) {
    __shared__ float red[256];
    int bc = blockIdx.x;
    const float4* p = (const float4*)(x + (size_t)bc * HWSZ);
    float s = 0.f;
    for (int i = threadIdx.x; i < HWSZ/4; i += 256) {
        float4 v = p[i];
        s += (v.x + v.y) + (v.z + v.w);
    }
    red[threadIdx.x] = s;
    __syncthreads();
    for (int off = 128; off > 0; off >>= 1) {
        if (threadIdx.x < off) red[threadIdx.x] += red[threadIdx.x + off];
        __syncthreads();
    }
    if (threadIdx.x == 0) g_pooled[bc] = red[0] * (1.0f / (float)HWSZ);
}

// ---------------------------------------------------------------
// Kernel 2: FCs. one block per b (float4 loads)
// ---------------------------------------------------------------
__global__ void fc_kernel(const float* __restrict__ fc1,
                          const float* __restrict__ fc2,
                          const float* __restrict__ fc2b) {
    __shared__ float ps[CC];
    __shared__ float hs[CC];
    int b = blockIdx.x, tid = threadIdx.x;
    ps[tid] = g_pooled[b*CC + tid];
    __syncthreads();
    {
        const float4* r1 = (const float4*)(fc1 + (size_t)tid * CC);
        float a = 0.f;
        #pragma unroll 8
        for (int j = 0; j < CC/4; j++) {
            float4 v = r1[j];
            a += ps[4*j]*v.x + ps[4*j+1]*v.y + ps[4*j+2]*v.z + ps[4*j+3]*v.w;
        }
        hs[tid] = fmaxf(a, 0.f);
    }
    __syncthreads();
    #pragma unroll
    for (int m4 = 0; m4 < 4; m4++) {
        int m = m4*CC + tid;                        // m = c*4 + t
        const float4* r2 = (const float4*)(fc2 + (size_t)m * CC);
        float s = fc2b[m];
        #pragma unroll 8
        for (int j = 0; j < CC/4; j++) {
            float4 v = r2[j];
            s += hs[4*j]*v.x + hs[4*j+1]*v.y + hs[4*j+2]*v.z + hs[4*j+3]*v.w;
        }
        g_kern[b*CC*4 + m] = s;
    }
}

// ---------------------------------------------------------------
// Kernel 3: fp16 A images. One thread per data quad (9 per row).
//   row = img*8192 + s*128 + o; word w holds kk {2w, 2w+1} as half2.
//   A[kk] = sigmoid(sum_t kern[b,c0+ci,t]*cog[o_g,t,r9]) * weight[o_g,c0+ci,r9]
//   words 18..23 (kk 36..47) zeroed; 24..27 pad never read.
// ---------------------------------------------------------------
__global__ void dynw_kernel(const float* __restrict__ cog,
                            const float* __restrict__ weight) {
    int idx = blockIdx.x * 256 + threadIdx.x;   // < 2^19 * 9
    int row = idx / 9;
    int g   = idx - row * 9;
    int o   = row & 127;
    int s   = (row >> 7) & 63;
    int img = row >> 13;
    int og = img & 1, b = img >> 1;
    int o_g = og*128 + o;
    int c0 = s*KCH;

    const float* cg = cog + (size_t)o_g * 36;
    float4 wq = *(const float4*)(weight + ((size_t)o_g*CC + c0)*9 + g*4);
    float wv[4] = {wq.x, wq.y, wq.z, wq.w};
    float d[4];
    #pragma unroll
    for (int u = 0; u < 4; u++) {
        int kk = g*4 + u;
        int ci = kk/9, r9 = kk - ci*9;
        const float4 kv = *(const float4*)(g_kern + ((size_t)b*CC + c0 + ci)*4);
        float sa = kv.x*cg[r9] + kv.y*cg[9+r9] + kv.z*cg[18+r9] + kv.w*cg[27+r9];
        sa = fminf(fmaxf(sa, -15.f), 15.f);
        d[u] = 1.0f + fast_exp(-sa);
    }
    float p01 = d[0]*d[1], p23 = d[2]*d[3];
    float P = p01 * p23;
    float rp; asm("rcp.approx.f32 %0, %1;" : "=f"(rp) : "f"(P));
    float v0 = wv[0] * (rp*d[1]*p23);
    float v1 = wv[1] * (rp*d[0]*p23);
    float v2 = wv[2] * (rp*p01*d[3]);
    float v3 = wv[3] * (rp*p01*d[2]);
    unsigned* dst = g_wA + (size_t)row * SWD + g*2;
    *(uint2*)dst = make_uint2(h2bits(v0, v1), h2bits(v2, v3));
    if (g < 3) {   // zero words 18..23 (kk 36..47, read by kstep 2)
        *(uint2*)(g_wA + (size_t)row * SWD + 18 + g*2) = make_uint2(0u, 0u);
    }
}

// ---------------------------------------------------------------
// Kernel 4: FP16 mma.sync implicit-GEMM conv.
// Stage = 4 channels x 9 taps -> 48 fp16 k (36 real), 3 ksteps of 16. 64 stages.
// Triple-buffered A (cp.async, wait_group 1), double-buffered B (LDG
// register prefetch + STS commit). Operands via ldmatrix.
// 8 warps = 4(M) x 2(N); warp tile 32 o x 56 px; mma m16n8k16.f16.
// ---------------------------------------------------------------
__global__ __launch_bounds__(256, 2)
void conv_kernel(const float* __restrict__ x, float* __restrict__ out) {
    extern __shared__ __align__(16) float dsm[];
    unsigned* As = (unsigned*)dsm;               // [3][A_WORDS]
    unsigned* Bs = (unsigned*)dsm + 3*A_WORDS;   // [2][B_WORDS]

    const int tid  = threadIdx.x;
    const int lane = tid & 31;
    const int wid  = tid >> 5;
    const int warpM = wid & 3;
    const int warpN = wid >> 2;
    const int tile = blockIdx.x, og = blockIdx.y, b = blockIdx.z;
    const int h0 = tile * 2;

    const float* xb = x + (size_t)b * CC * HWSZ;
    const uint4* gA = (const uint4*)g_wA + (size_t)((b*2 + og) * NST2) * A_CH;

    // ---- B feed mapping: half = tid/112 (kk base = half*20), px = tid%112 ----
    const int half = tid / 112;          // 0,1 active; 2 inactive
    const int px   = tid - half*112;
    const bool bact = (tid < 224);
    const int rr = px / 56, cw = px % 56;
    const int ghb = h0 + rr - 1, gwb = cw - 1;
    const int cbase = ghb*WW + gwb;

    unsigned vmask = 0;
    {
        #pragma unroll
        for (int u = 0; u < 20; u++) {
            int kk = half*20 + u;
            int ci = kk/9, r9 = kk - ci*9;
            int i3 = r9/3, j3 = r9 - i3*3;
            int gh = ghb + i3, gw = gwb + j3;
            bool ok = bact && (kk < 36) && (gh >= 0) && (gh < HH) && (gw >= 0) && (gw < WW);
            vmask |= (ok ? 1u : 0u) << u;
        }
    }

    float acc[2][7][4];
    #pragma unroll
    for (int m = 0; m < 2; m++)
        #pragma unroll
        for (int n = 0; n < 7; n++)
            #pragma unroll
            for (int q = 0; q < 4; q++) acc[m][n][q] = 0.f;

    // ---- ldmatrix lane-address offsets (bytes) ----
    // A x4: lanes 0-15 -> rows (lane&15) @k0; 16-31 -> same rows @+16B
    const unsigned aoffL = (unsigned)((warpM*32 + (lane & 15))*112 + (lane >> 4)*16);
    // B x4 (n-pair): g=lane>>3: row (g>>1)*8 + (lane&7), koff (g&1)*16
    const unsigned boffL = (unsigned)((warpN*56 + ((lane >> 4))*8 + (lane & 7))*112
                                     + (((lane >> 3) & 1))*16);
    // B x2 (last n-tile, rows 48..55): lanes 0-15 used
    const unsigned boffL2 = (unsigned)((warpN*56 + 48 + (lane & 7))*112
                                      + (((lane >> 3) & 1))*16);

    // compile-time offset prefetch: KKB is a literal 0 or 20
    #define PF_B(XS, KKB)                                                        \
        _Pragma("unroll")                                                        \
        for (int u_ = 0; u_ < 20; u_++) {                                        \
            const int kk_ = (KKB) + u_;                                          \
            const int off_ = (kk_/9)*HWSZ + (((kk_%9))/3)*WW + ((kk_%9)%3);      \
            vreg[u_] = ((vmask >> u_) & 1) ? __ldg((XS) + cbase + off_) : 0.f;   \
        }

    #define ISSUE_A(S, BUF)                                                      \
    {                                                                            \
        const uint4* srcA_ = gA + (size_t)(S) * A_CH;                            \
        unsigned dA_ = smem_u32(As) + (unsigned)(BUF)*A_BYTES;                   \
        _Pragma("unroll")                                                        \
        for (int i_ = 0; i_ < 4; i_++) {                                         \
            int ch_ = tid + i_ * 256;                                            \
            if (ch_ < A_CH) cp_async16(dA_ + ch_*16, srcA_ + ch_);               \
        }                                                                        \
        asm volatile("cp.async.commit_group;");                                  \
    }

    // pack 20 fp32 -> 10 half2 words; half0 -> bytes 0..39, half1 -> 40..79 of row
    #define COMMIT_B(BUF)                                                        \
    if (bact) {                                                                  \
        unsigned w_[10];                                                         \
        _Pragma("unroll")                                                        \
        for (int i_ = 0; i_ < 10; i_++)                                          \
            w_[i_] = h2bits(vreg[2*i_], vreg[2*i_+1]);                           \
        unsigned db_ = smem_u32(Bs) + (BUF)*B_BYTES + px*112;                    \
        if (half == 0) {                                                         \
            STS128(db_ + 0,  w_[0], w_[1], w_[2], w_[3]);                        \
            STS128(db_ + 16, w_[4], w_[5], w_[6], w_[7]);                        \
            STS64 (db_ + 32, w_[8], w_[9]);                                      \
        } else {                                                                 \
            STS64 (db_ + 40, w_[0], w_[1]);                                      \
            STS128(db_ + 48, w_[2], w_[3], w_[4], w_[5]);                        \
            STS128(db_ + 64, w_[6], w_[7], w_[8], w_[9]);                        \
        }                                                                        \
    }

    // ---- zero B words 20..23 (kk 40..47, read by kstep 2) once, both buffers ----
    if (tid < 112) {
        STS128(smem_u32(Bs) + 0*B_BYTES + tid*112 + 80, 0u, 0u, 0u, 0u);
        STS128(smem_u32(Bs) + 1*B_BYTES + tid*112 + 80, 0u, 0u, 0u, 0u);
    }

    // ---- prologue: A(0)->buf0, A(1)->buf1, B(0)->Bbuf0 ----
    {
        float vreg[20];
        ISSUE_A(0, 0);
        ISSUE_A(1, 1);
        if (bact) {
            const float* xs = xb;
            if (half == 0) { PF_B(xs, 0) } else { PF_B(xs, 20) }
        }
        COMMIT_B(0);
        asm volatile("cp.async.wait_group 1;");   // A(0) done; A(1) may be pending
        __syncthreads();
    }

    int pr = 0;   // A read buffer = s % 3
    for (int s = 0; s < NST2; s++) {
        const int q = s & 1;
        float vreg[20];

        // ---- issue A(s+2) + prefetch B(s+1) into registers ----
        if (s + 2 < NST2) {
            int pi = pr + 2; if (pi >= 3) pi -= 3;
            ISSUE_A(s + 2, pi);
        }
        if (s + 1 < NST2 && bact) {
            const float* xs = xb + (size_t)(s + 1) * (KCH*HWSZ);
            if (half == 0) { PF_B(xs, 0) } else { PF_B(xs, 20) }
        }

        // ---- MMA on stage s: 3 ksteps of K=16, operands via ldmatrix ----
        const unsigned Ab = smem_u32(As) + (unsigned)pr*A_BYTES;
        const unsigned Bb = smem_u32(Bs) + (unsigned)q*B_BYTES;
        #pragma unroll
        for (int ks = 0; ks < 3; ks++) {
            unsigned af[2][4], bf[7][2];
            LDSM4(af[0][0], af[0][1], af[0][2], af[0][3], Ab + aoffL + ks*32);
            LDSM4(af[1][0], af[1][1], af[1][2], af[1][3], Ab + aoffL + 1792 + ks*32);
            LDSM4(bf[0][0], bf[0][1], bf[1][0], bf[1][1], Bb + boffL + ks*32);
            LDSM4(bf[2][0], bf[2][1], bf[3][0], bf[3][1], Bb + boffL + 1792 + ks*32);
            LDSM4(bf[4][0], bf[4][1], bf[5][0], bf[5][1], Bb + boffL + 3584 + ks*32);
            LDSM2(bf[6][0], bf[6][1], Bb + boffL2 + ks*32);
            #pragma unroll
            for (int m = 0; m < 2; m++)
                #pragma unroll
                for (int n = 0; n < 7; n++)
                    asm volatile(
                        "mma.sync.aligned.m16n8k16.row.col.f32.f16.f16.f32 "
                        "{%0,%1,%2,%3}, {%4,%5,%6,%7}, {%8,%9}, {%0,%1,%2,%3};"
                        : "+f"(acc[m][n][0]), "+f"(acc[m][n][1]),
                          "+f"(acc[m][n][2]), "+f"(acc[m][n][3])
                        : "r"(af[m][0]), "r"(af[m][1]), "r"(af[m][2]), "r"(af[m][3]),
                          "r"(bf[n][0]), "r"(bf[n][1]));
        }

        // ---- commit prefetched B to the other buffer ----
        if (s + 1 < NST2) COMMIT_B(q ^ 1);

        if (s + 2 < NST2) { asm volatile("cp.async.wait_group 1;"); }
        else              { asm volatile("cp.async.wait_group 0;"); }
        __syncthreads();
        pr++; if (pr == 3) pr = 0;
    }
    #undef ISSUE_A
    #undef COMMIT_B
    #undef PF_B

    // ---- epilogue: fragments -> gmem (all px of a warp share one h row) ----
    const int h = h0 + warpN;
    const int wbase = (lane & 3) * 2;
    #pragma unroll
    for (int m = 0; m < 2; m++) {
        int o = og*128 + warpM*32 + m*16 + (lane >> 2);
        float* r0 = out + ((size_t)b*OO + o)*HWSZ + h*WW;
        float* r1 = out + ((size_t)b*OO + o + 8)*HWSZ + h*WW;
        #pragma unroll
        for (int n = 0; n < 7; n++) {
            int w = n*8 + wbase;
            *(float2*)(r0 + w) = make_float2(acc[m][n][0], acc[m][n][1]);
            *(float2*)(r1 + w) = make_float2(acc[m][n][2], acc[m][n][3]);
        }
    }
}

// ---------------------------------------------------------------
extern "C" void kernel_launch(void* const* d_in, const int* in_sizes, int n_in,
                              void* d_out, int out_size) {
    const float* x      = (const float*)d_in[0];
    const float* fc1_w  = (const float*)d_in[1];
    const float* fc2_w  = (const float*)d_in[2];
    const float* fc2_b  = (const float*)d_in[3];
    const float* cog_w  = (const float*)d_in[4];
    const float* weight = (const float*)d_in[5];
    float* out = (float*)d_out;

    cudaFuncSetAttribute(conv_kernel, cudaFuncAttributeMaxDynamicSharedMemorySize, SMEM_CONV);

    pool_kernel<<<BB*CC, 256>>>(x);
    fc_kernel<<<BB, 256>>>(fc1_w, fc2_w, fc2_b);
    dynw_kernel<<<18432, 256>>>(cog_w, weight);   // 2^19 rows x 9 quads
    {
        dim3 grid(28, 2, BB);
        conv_kernel<<<grid, 256, SMEM_CONV>>>(x, out);
    }
}

// round 16
// speedup vs baseline: 3.3877x; 1.0595x over previous
#include <cuda_runtime.h>
#include <cuda_bf16.h>
#include <cuda_fp16.h>
#include <cstdint>
#include <cstddef>
#include <math.h>

#define BB 32
#define CC 256
#define OO 256
#define HH 56
#define WW 56
#define HWSZ 3136
#define KCH 8              // channels per stage
#define NST3 32            // stages (256/8)
#define SWD 44             // 32b words per row: 40 data words (80 fp16: 72 real + 8 zero) + 4 pad
#define ROWB 176           // bytes per row
#define A_WORDS (128*SWD)  // 5632
#define B_WORDS (112*SWD)  // 4928
#define A_BYTES (A_WORDS*4)   // 22528
#define B_BYTES (B_WORDS*4)   // 19712
#define A_CH (A_BYTES/16)     // 1408 16B chunks
#define SMEM_CONV (3*A_BYTES + 2*B_BYTES)   // 107008 B

// ---- scratch ----
__device__ float g_pooled[BB*CC];
__device__ float g_kern[BB*CC*4];
__device__ unsigned g_wA[(size_t)BB*2*NST3*128*SWD];   // fp16 A images, ~46MB

// ---- helpers ----
__device__ __forceinline__ unsigned smem_u32(const void* p) {
    return (unsigned)__cvta_generic_to_shared((void*)p);
}
__device__ __forceinline__ void cp_async16(unsigned dst, const void* src) {
    asm volatile("cp.async.cg.shared.global [%0], [%1], 16;" :: "r"(dst), "l"(src));
}
__device__ __forceinline__ unsigned h2bits(float lo, float hi) {
    __half2 h = __floats2half2_rn(lo, hi);
    return *(unsigned*)&h;
}
// FFMA-only exp(x) for x in [-16, 16] (no MUFU)
__device__ __forceinline__ float fast_exp(float x) {
    float t = x * 1.4426950408889634f;          // log2(e)
    float fi = floorf(t);
    float f = t - fi;
    float p = 1.5403530393381606e-4f;
    p = fmaf(p, f, 1.3333558146428443e-3f);
    p = fmaf(p, f, 9.618129107628477e-3f);
    p = fmaf(p, f, 5.550410866482158e-2f);
    p = fmaf(p, f, 2.402265069591007e-1f);
    p = fmaf(p, f, 6.931471805599453e-1f);
    p = fmaf(p, f, 1.0f);
    int ei = (int)fi;
    return __int_as_float((ei + 127) << 23) * p;
}
#define STS128(a, r0, r1, r2, r3) asm volatile("st.shared.v4.b32 [%0], {%1,%2,%3,%4};" :: "r"(a), "r"(r0), "r"(r1), "r"(r2), "r"(r3) : "memory")
#define STS64(a, r0, r1) asm volatile("st.shared.v2.b32 [%0], {%1,%2};" :: "r"(a), "r"(r0), "r"(r1) : "memory")
#define STG128(a, r0, r1, r2, r3) asm volatile("st.global.v4.u32 [%0], {%1,%2,%3,%4};" :: "l"(a), "r"(r0), "r"(r1), "r"(r2), "r"(r3) : "memory")
#define LDSM4(r0, r1, r2, r3, addr) asm volatile( \
    "ldmatrix.sync.aligned.m8n8.x4.shared.b16 {%0,%1,%2,%3}, [%4];" \
    : "=r"(r0), "=r"(r1), "=r"(r2), "=r"(r3) : "r"(addr))
#define LDSM2(r0, r1, addr) asm volatile( \
    "ldmatrix.sync.aligned.m8n8.x2.shared.b16 {%0,%1}, [%2];" \
    : "=r"(r0), "=r"(r1) : "r"(addr))

// ---------------------------------------------------------------
// Kernel 1: global average pool. one block per (b,c)
// ---------------------------------------------------------------
__global__ void pool_kernel(const float* __restrict__ x) {
    __shared__ float red[256];
    int bc = blockIdx.x;
    const float4* p = (const float4*)(x + (size_t)bc * HWSZ);
    float s = 0.f;
    for (int i = threadIdx.x; i < HWSZ/4; i += 256) {
        float4 v = p[i];
        s += (v.x + v.y) + (v.z + v.w);
    }
    red[threadIdx.x] = s;
    __syncthreads();
    for (int off = 128; off > 0; off >>= 1) {
        if (threadIdx.x < off) red[threadIdx.x] += red[threadIdx.x + off];
        __syncthreads();
    }
    if (threadIdx.x == 0) g_pooled[bc] = red[0] * (1.0f / (float)HWSZ);
}

// ---------------------------------------------------------------
// Kernel 2: FCs. one block per b (float4 loads)
// ---------------------------------------------------------------
__global__ void fc_kernel(const float* __restrict__ fc1,
                          const float* __restrict__ fc2,
                          const float* __restrict__ fc2b) {
    __shared__ float ps[CC];
    __shared__ float hs[CC];
    int b = blockIdx.x, tid = threadIdx.x;
    ps[tid] = g_pooled[b*CC + tid];
    __syncthreads();
    {
        const float4* r1 = (const float4*)(fc1 + (size_t)tid * CC);
        float a = 0.f;
        #pragma unroll 8
        for (int j = 0; j < CC/4; j++) {
            float4 v = r1[j];
            a += ps[4*j]*v.x + ps[4*j+1]*v.y + ps[4*j+2]*v.z + ps[4*j+3]*v.w;
        }
        hs[tid] = fmaxf(a, 0.f);
    }
    __syncthreads();
    #pragma unroll
    for (int m4 = 0; m4 < 4; m4++) {
        int m = m4*CC + tid;                        // m = c*4 + t
        const float4* r2 = (const float4*)(fc2 + (size_t)m * CC);
        float s = fc2b[m];
        #pragma unroll 8
        for (int j = 0; j < CC/4; j++) {
            float4 v = r2[j];
            s += hs[4*j]*v.x + hs[4*j+1]*v.y + hs[4*j+2]*v.z + hs[4*j+3]*v.w;
        }
        g_kern[b*CC*4 + m] = s;
    }
}

// ---------------------------------------------------------------
// Kernel 3: fp16 A images. One thread per 16B quad (8 kk values; 9 per row).
//   row = img*4096 + s*128 + o; word w holds kk {2w, 2w+1} as half2.
//   A[kk] = sigmoid(sum_t kern[b,c0+ci,t]*cog[o_g,t,r9]) * weight[o_g,c0+ci,r9]
//   kk = ci*9 + r9, ci 0..7. words 36..43 zeroed by g==0 thread.
// ---------------------------------------------------------------
__global__ void dynw_kernel(const float* __restrict__ cog,
                            const float* __restrict__ weight) {
    int idx = blockIdx.x * 256 + threadIdx.x;   // < 262144 * 9
    int row = idx / 9;
    int g   = idx - row * 9;                     // quad id: kk = g*8 .. g*8+7
    int o   = row & 127;
    int s   = (row >> 7) & 31;
    int img = row >> 12;
    int og = img & 1, b = img >> 1;
    int o_g = og*128 + o;
    int c0 = s*KCH;

    const float* cg = cog + (size_t)o_g * 36;
    const float4* wp = (const float4*)(weight + ((size_t)o_g*CC + c0)*9 + g*8);
    float4 wq0 = wp[0], wq1 = wp[1];
    float wv[8] = {wq0.x, wq0.y, wq0.z, wq0.w, wq1.x, wq1.y, wq1.z, wq1.w};
    float d[8];
    #pragma unroll
    for (int u = 0; u < 8; u++) {
        int kk = g*8 + u;
        int ci = kk/9, r9 = kk - ci*9;
        const float4 kv = *(const float4*)(g_kern + ((size_t)b*CC + c0 + ci)*4);
        float sa = kv.x*cg[r9] + kv.y*cg[9+r9] + kv.z*cg[18+r9] + kv.w*cg[27+r9];
        sa = fminf(fmaxf(sa, -15.f), 15.f);
        d[u] = 1.0f + fast_exp(-sa);
    }
    unsigned w[4];
    #pragma unroll
    for (int h4 = 0; h4 < 2; h4++) {
        float d0 = d[h4*4], d1 = d[h4*4+1], d2 = d[h4*4+2], d3 = d[h4*4+3];
        float p01 = d0*d1, p23 = d2*d3;
        float P = p01 * p23;
        float rp; asm("rcp.approx.f32 %0, %1;" : "=f"(rp) : "f"(P));
        float v0 = wv[h4*4+0] * (rp*d1*p23);
        float v1 = wv[h4*4+1] * (rp*d0*p23);
        float v2 = wv[h4*4+2] * (rp*p01*d3);
        float v3 = wv[h4*4+3] * (rp*p01*d2);
        w[h4*2+0] = h2bits(v0, v1);
        w[h4*2+1] = h2bits(v2, v3);
    }
    unsigned* dst = g_wA + (size_t)row * SWD + g*4;
    STG128(dst, w[0], w[1], w[2], w[3]);
    if (g == 0) {   // zero words 36..43 (kk 72..79 zero-k tail + pad)
        unsigned* z = g_wA + (size_t)row * SWD + 36;
        STG128(z, 0u, 0u, 0u, 0u);
        STG128(z + 4, 0u, 0u, 0u, 0u);
    }
}

// ---------------------------------------------------------------
// Kernel 4: FP16 mma.sync implicit-GEMM conv.
// Stage = 8 channels x 9 taps -> 80 fp16 k (72 real), 5 ksteps of 16. 32 stages.
// Triple-buffered A (cp.async, wait_group 1), double-buffered B (LDG
// register prefetch in 2 passes of 20+16, STS commit interleaved with MMA).
// 8 warps = 4(M) x 2(N); warp tile 32 o x 56 px; mma m16n8k16.f16 via ldmatrix.
// ---------------------------------------------------------------
__global__ __launch_bounds__(256, 2)
void conv_kernel(const float* __restrict__ x, float* __restrict__ out) {
    extern __shared__ __align__(16) float dsm[];
    unsigned* As = (unsigned*)dsm;               // [3][A_WORDS]
    unsigned* Bs = (unsigned*)dsm + 3*A_WORDS;   // [2][B_WORDS]

    const int tid  = threadIdx.x;
    const int lane = tid & 31;
    const int wid  = tid >> 5;
    const int warpM = wid & 3;
    const int warpN = wid >> 2;
    const int tile = blockIdx.x, og = blockIdx.y, b = blockIdx.z;
    const int h0 = tile * 2;

    const float* xb = x + (size_t)b * CC * HWSZ;
    const uint4* gA = (const uint4*)g_wA + (size_t)((b*2 + og) * NST3) * A_CH;

    // ---- B feed mapping: half = tid/112 (kk base = half*36), px = tid%112 ----
    const int half = tid / 112;          // 0,1 active; 2 inactive
    const int px   = tid - half*112;
    const bool bact = (tid < 224);
    const int rr = px / 56, cw = px % 56;
    const int ghb = h0 + rr - 1, gwb = cw - 1;
    const int cbase = ghb*WW + gwb;

    unsigned vmask0 = 0, vmask1 = 0;
    {
        #pragma unroll
        for (int u = 0; u < 20; u++) {
            int kk = half*36 + u;
            int ci = kk/9, r9 = kk - ci*9;
            int i3 = r9/3, j3 = r9 - i3*3;
            int gh = ghb + i3, gw = gwb + j3;
            bool ok = bact && (gh >= 0) && (gh < HH) && (gw >= 0) && (gw < WW);
            vmask0 |= (ok ? 1u : 0u) << u;
        }
        #pragma unroll
        for (int u = 0; u < 16; u++) {
            int kk = half*36 + 20 + u;
            int ci = kk/9, r9 = kk - ci*9;
            int i3 = r9/3, j3 = r9 - i3*3;
            int gh = ghb + i3, gw = gwb + j3;
            bool ok = bact && (gh >= 0) && (gh < HH) && (gw >= 0) && (gw < WW);
            vmask1 |= (ok ? 1u : 0u) << u;
        }
    }

    float acc[2][7][4];
    #pragma unroll
    for (int m = 0; m < 2; m++)
        #pragma unroll
        for (int n = 0; n < 7; n++)
            #pragma unroll
            for (int q = 0; q < 4; q++) acc[m][n][q] = 0.f;

    // ---- ldmatrix lane-address offsets (bytes), row stride 176B ----
    const unsigned aoffL = (unsigned)((warpM*32 + (lane & 15))*ROWB + (lane >> 4)*16);
    const unsigned boffL = (unsigned)((warpN*56 + ((lane >> 4))*8 + (lane & 7))*ROWB
                                     + (((lane >> 3) & 1))*16);
    const unsigned boffL2 = (unsigned)((warpN*56 + 48 + (lane & 7))*ROWB
                                      + (((lane >> 3) & 1))*16);

    // compile-time offset prefetch; K0 is a literal
    #define PF_B20(XS, K0)                                                       \
        _Pragma("unroll")                                                        \
        for (int u_ = 0; u_ < 20; u_++) {                                        \
            const int kk_ = (K0) + u_;                                           \
            const int off_ = (kk_/9)*HWSZ + (((kk_%9))/3)*WW + ((kk_%9)%3);      \
            vreg[u_] = ((vmask0 >> u_) & 1) ? __ldg((XS) + cbase + off_) : 0.f;  \
        }
    #define PF_B16(XS, K0)                                                       \
        _Pragma("unroll")                                                        \
        for (int u_ = 0; u_ < 16; u_++) {                                        \
            const int kk_ = (K0) + u_;                                           \
            const int off_ = (kk_/9)*HWSZ + (((kk_%9))/3)*WW + ((kk_%9)%3);      \
            vreg[u_] = ((vmask1 >> u_) & 1) ? __ldg((XS) + cbase + off_) : 0.f;  \
        }

    #define ISSUE_A(S, BUF)                                                      \
    {                                                                            \
        const uint4* srcA_ = gA + (size_t)(S) * A_CH;                            \
        unsigned dA_ = smem_u32(As) + (unsigned)(BUF)*A_BYTES;                   \
        _Pragma("unroll")                                                        \
        for (int i_ = 0; i_ < 6; i_++) {                                         \
            int ch_ = tid + i_ * 256;                                            \
            if (ch_ < A_CH) cp_async16(dA_ + ch_*16, srcA_ + ch_);               \
        }                                                                        \
        asm volatile("cp.async.commit_group;");                                  \
    }

    // pass0: 20 fp32 -> words (half*18 .. +9) of the row
    #define COMMIT_B0(BUF)                                                       \
    if (bact) {                                                                  \
        unsigned w_[10];                                                         \
        _Pragma("unroll")                                                        \
        for (int i_ = 0; i_ < 10; i_++)                                          \
            w_[i_] = h2bits(vreg[2*i_], vreg[2*i_+1]);                           \
        unsigned db_ = smem_u32(Bs) + (BUF)*B_BYTES + px*ROWB;                   \
        if (half == 0) {                                                         \
            STS128(db_ + 0,  w_[0], w_[1], w_[2], w_[3]);                        \
            STS128(db_ + 16, w_[4], w_[5], w_[6], w_[7]);                        \
            STS64 (db_ + 32, w_[8], w_[9]);                                      \
        } else {                                                                 \
            STS64 (db_ + 72, w_[0], w_[1]);                                      \
            STS128(db_ + 80, w_[2], w_[3], w_[4], w_[5]);                        \
            STS128(db_ + 96, w_[6], w_[7], w_[8], w_[9]);                        \
        }                                                                        \
    }
    // pass1: 16 fp32 -> words (half*18+10 .. +17)
    #define COMMIT_B1(BUF)                                                       \
    if (bact) {                                                                  \
        unsigned w_[8];                                                          \
        _Pragma("unroll")                                                        \
        for (int i_ = 0; i_ < 8; i_++)                                           \
            w_[i_] = h2bits(vreg[2*i_], vreg[2*i_+1]);                           \
        unsigned db_ = smem_u32(Bs) + (BUF)*B_BYTES + px*ROWB;                   \
        if (half == 0) {                                                         \
            STS64 (db_ + 40, w_[0], w_[1]);                                      \
            STS128(db_ + 48, w_[2], w_[3], w_[4], w_[5]);                        \
            STS64 (db_ + 64, w_[6], w_[7]);                                      \
        } else {                                                                 \
            STS128(db_ + 112, w_[0], w_[1], w_[2], w_[3]);                       \
            STS128(db_ + 128, w_[4], w_[5], w_[6], w_[7]);                       \
        }                                                                        \
    }

    #define MMA_KS(ks)                                                           \
    {                                                                            \
        unsigned af[2][4], bf[7][2];                                             \
        LDSM4(af[0][0], af[0][1], af[0][2], af[0][3], Ab + aoffL + (ks)*32);     \
        LDSM4(af[1][0], af[1][1], af[1][2], af[1][3], Ab + aoffL + 16*ROWB + (ks)*32); \
        LDSM4(bf[0][0], bf[0][1], bf[1][0], bf[1][1], Bb + boffL + (ks)*32);     \
        LDSM4(bf[2][0], bf[2][1], bf[3][0], bf[3][1], Bb + boffL + 16*ROWB + (ks)*32); \
        LDSM4(bf[4][0], bf[4][1], bf[5][0], bf[5][1], Bb + boffL + 32*ROWB + (ks)*32); \
        LDSM2(bf[6][0], bf[6][1], Bb + boffL2 + (ks)*32);                        \
        _Pragma("unroll")                                                        \
        for (int m = 0; m < 2; m++)                                              \
            _Pragma("unroll")                                                    \
            for (int n = 0; n < 7; n++)                                          \
                asm volatile(                                                    \
                    "mma.sync.aligned.m16n8k16.row.col.f32.f16.f16.f32 "         \
                    "{%0,%1,%2,%3}, {%4,%5,%6,%7}, {%8,%9}, {%0,%1,%2,%3};"      \
                    : "+f"(acc[m][n][0]), "+f"(acc[m][n][1]),                    \
                      "+f"(acc[m][n][2]), "+f"(acc[m][n][3])                     \
                    : "r"(af[m][0]), "r"(af[m][1]), "r"(af[m][2]), "r"(af[m][3]),\
                      "r"(bf[n][0]), "r"(bf[n][1]));                             \
    }

    // ---- zero B words 36..43 (kk 72..79 + pad) once, both buffers ----
    if (tid < 112) {
        STS128(smem_u32(Bs) + 0*B_BYTES + tid*ROWB + 144, 0u, 0u, 0u, 0u);
        STS128(smem_u32(Bs) + 0*B_BYTES + tid*ROWB + 160, 0u, 0u, 0u, 0u);
        STS128(smem_u32(Bs) + 1*B_BYTES + tid*ROWB + 144, 0u, 0u, 0u, 0u);
        STS128(smem_u32(Bs) + 1*B_BYTES + tid*ROWB + 160, 0u, 0u, 0u, 0u);
    }

    // ---- prologue: A(0)->buf0, A(1)->buf1, B(0)->Bbuf0 ----
    {
        float vreg[20];
        ISSUE_A(0, 0);
        ISSUE_A(1, 1);
        if (bact) {
            if (half == 0) { PF_B20(xb, 0)  } else { PF_B20(xb, 36) }
        }
        COMMIT_B0(0);
        if (bact) {
            if (half == 0) { PF_B16(xb, 20) } else { PF_B16(xb, 56) }
        }
        COMMIT_B1(0);
        asm volatile("cp.async.wait_group 1;");   // A(0) done; A(1) may be pending
        __syncthreads();
    }

    int pr = 0;   // A read buffer = s % 3
    for (int s = 0; s < NST3; s++) {
        const int q = s & 1;
        float vreg[20];

        // ---- issue A(s+2) ----
        if (s + 2 < NST3) {
            int pi = pr + 2; if (pi >= 3) pi -= 3;
            ISSUE_A(s + 2, pi);
        }
        const float* xs = xb + (size_t)(s + 1) * (KCH*HWSZ);
        // ---- B(s+1) pass0 prefetch ----
        if (s + 1 < NST3 && bact) {
            if (half == 0) { PF_B20(xs, 0) } else { PF_B20(xs, 36) }
        }

        const unsigned Ab = smem_u32(As) + (unsigned)pr*A_BYTES;
        const unsigned Bb = smem_u32(Bs) + (unsigned)q*B_BYTES;
        MMA_KS(0)
        MMA_KS(1)

        if (s + 1 < NST3) {
            COMMIT_B0(q ^ 1);
            if (bact) {
                if (half == 0) { PF_B16(xs, 20) } else { PF_B16(xs, 56) }
            }
        }

        MMA_KS(2)
        MMA_KS(3)
        MMA_KS(4)

        if (s + 1 < NST3) COMMIT_B1(q ^ 1);

        if (s + 2 < NST3) { asm volatile("cp.async.wait_group 1;"); }
        else              { asm volatile("cp.async.wait_group 0;"); }
        __syncthreads();
        pr++; if (pr == 3) pr = 0;
    }
    #undef ISSUE_A
    #undef COMMIT_B0
    #undef COMMIT_B1
    #undef PF_B20
    #undef PF_B16
    #undef MMA_KS

    // ---- epilogue: fragments -> gmem (all px of a warp share one h row) ----
    const int h = h0 + warpN;
    const int wbase = (lane & 3) * 2;
    #pragma unroll
    for (int m = 0; m < 2; m++) {
        int o = og*128 + warpM*32 + m*16 + (lane >> 2);
        float* r0 = out + ((size_t)b*OO + o)*HWSZ + h*WW;
        float* r1 = out + ((size_t)b*OO + o + 8)*HWSZ + h*WW;
        #pragma unroll
        for (int n = 0; n < 7; n++) {
            int w = n*8 + wbase;
            *(float2*)(r0 + w) = make_float2(acc[m][n][0], acc[m][n][1]);
            *(float2*)(r1 + w) = make_float2(acc[m][n][2], acc[m][n][3]);
        }
    }
}

// ---------------------------------------------------------------
extern "C" void kernel_launch(void* const* d_in, const int* in_sizes, int n_in,
                              void* d_out, int out_size) {
    const float* x      = (const float*)d_in[0];
    const float* fc1_w  = (const float*)d_in[1];
    const float* fc2_w  = (const float*)d_in[2];
    const float* fc2_b  = (const float*)d_in[3];
    const float* cog_w  = (const float*)d_in[4];
    const float* weight = (const float*)d_in[5];
    float* out = (float*)d_out;

    cudaFuncSetAttribute(conv_kernel, cudaFuncAttributeMaxDynamicSharedMemorySize, SMEM_CONV);

    pool_kernel<<<BB*CC, 256>>>(x);
    fc_kernel<<<BB, 256>>>(fc1_w, fc2_w, fc2_b);
    dynw_kernel<<<9216, 256>>>(cog_w, weight);   // 262144 rows x 9 quads
    {
        dim3 grid(28, 2, BB);
        conv_kernel<<<grid, 256, SMEM_CONV>>>(x, out);
    }
}

// round 17
// speedup vs baseline: 3.5996x; 1.0625x over previous
#include <cuda_runtime.h>
#include <cuda_bf16.h>
#include <cuda_fp16.h>
#include <cstdint>
#include <cstddef>
#include <math.h>

#define BB 32
#define CC 256
#define OO 256
#define HH 56
#define WW 56
#define HWSZ 3136
#define KCH 8              // channels per stage
#define NST3 32            // stages (256/8)
#define SWD 44             // 32b words per row: 40 data (80 fp16: 72 real + 8 zero) + 4 pad
#define ROWB 176           // bytes per row
#define A_ROWS 256         // merged og: full 256 outputs per CTA
#define A_WORDS (A_ROWS*SWD)  // 11264
#define B_WORDS (112*SWD)     // 4928
#define A_BYTES (A_WORDS*4)   // 45056
#define B_BYTES (B_WORDS*4)   // 19712
#define A_CH (A_BYTES/16)     // 2816 16B chunks (= 11*256)
#define SMEM_CONV (3*A_BYTES + 2*B_BYTES)   // 174592 B

// ---- scratch ----
__device__ float g_pooled[BB*CC];
__device__ float g_kern[BB*CC*4];
__device__ unsigned g_wA[(size_t)BB*NST3*A_ROWS*SWD];   // fp16 A images, ~46MB

// ---- helpers ----
__device__ __forceinline__ unsigned smem_u32(const void* p) {
    return (unsigned)__cvta_generic_to_shared((void*)p);
}
__device__ __forceinline__ void cp_async16(unsigned dst, const void* src) {
    asm volatile("cp.async.cg.shared.global [%0], [%1], 16;" :: "r"(dst), "l"(src));
}
__device__ __forceinline__ unsigned h2bits(float lo, float hi) {
    __half2 h = __floats2half2_rn(lo, hi);
    return *(unsigned*)&h;
}
// FFMA-only exp(x) for x in [-16, 16] (no MUFU)
__device__ __forceinline__ float fast_exp(float x) {
    float t = x * 1.4426950408889634f;          // log2(e)
    float fi = floorf(t);
    float f = t - fi;
    float p = 1.5403530393381606e-4f;
    p = fmaf(p, f, 1.3333558146428443e-3f);
    p = fmaf(p, f, 9.618129107628477e-3f);
    p = fmaf(p, f, 5.550410866482158e-2f);
    p = fmaf(p, f, 2.402265069591007e-1f);
    p = fmaf(p, f, 6.931471805599453e-1f);
    p = fmaf(p, f, 1.0f);
    int ei = (int)fi;
    return __int_as_float((ei + 127) << 23) * p;
}
#define STS128(a, r0, r1, r2, r3) asm volatile("st.shared.v4.b32 [%0], {%1,%2,%3,%4};" :: "r"(a), "r"(r0), "r"(r1), "r"(r2), "r"(r3) : "memory")
#define STS64(a, r0, r1) asm volatile("st.shared.v2.b32 [%0], {%1,%2};" :: "r"(a), "r"(r0), "r"(r1) : "memory")
#define STG128(a, r0, r1, r2, r3) asm volatile("st.global.v4.u32 [%0], {%1,%2,%3,%4};" :: "l"(a), "r"(r0), "r"(r1), "r"(r2), "r"(r3) : "memory")
#define LDSM4(r0, r1, r2, r3, addr) asm volatile( \
    "ldmatrix.sync.aligned.m8n8.x4.shared.b16 {%0,%1,%2,%3}, [%4];" \
    : "=r"(r0), "=r"(r1), "=r"(r2), "=r"(r3) : "r"(addr))
#define LDSM2(r0, r1, addr) asm volatile( \
    "ldmatrix.sync.aligned.m8n8.x2.shared.b16 {%0,%1}, [%2];" \
    : "=r"(r0), "=r"(r1) : "r"(addr))
#define MMA16(acc, a0, a1, a2, a3, b0, b1) asm volatile( \
    "mma.sync.aligned.m16n8k16.row.col.f32.f16.f16.f32 " \
    "{%0,%1,%2,%3}, {%4,%5,%6,%7}, {%8,%9}, {%0,%1,%2,%3};" \
    : "+f"((acc)[0]), "+f"((acc)[1]), "+f"((acc)[2]), "+f"((acc)[3]) \
    : "r"(a0), "r"(a1), "r"(a2), "r"(a3), "r"(b0), "r"(b1))

// ---------------------------------------------------------------
// Kernel 1: global average pool. one block per (b,c)
// ---------------------------------------------------------------
__global__ void pool_kernel(const float* __restrict__ x) {
    __shared__ float red[256];
    int bc = blockIdx.x;
    const float4* p = (const float4*)(x + (size_t)bc * HWSZ);
    float s = 0.f;
    for (int i = threadIdx.x; i < HWSZ/4; i += 256) {
        float4 v = p[i];
        s += (v.x + v.y) + (v.z + v.w);
    }
    red[threadIdx.x] = s;
    __syncthreads();
    for (int off = 128; off > 0; off >>= 1) {
        if (threadIdx.x < off) red[threadIdx.x] += red[threadIdx.x + off];
        __syncthreads();
    }
    if (threadIdx.x == 0) g_pooled[bc] = red[0] * (1.0f / (float)HWSZ);
}

// ---------------------------------------------------------------
// Kernel 2: FCs. one block per b (float4 loads)
// ---------------------------------------------------------------
__global__ void fc_kernel(const float* __restrict__ fc1,
                          const float* __restrict__ fc2,
                          const float* __restrict__ fc2b) {
    __shared__ float ps[CC];
    __shared__ float hs[CC];
    int b = blockIdx.x, tid = threadIdx.x;
    ps[tid] = g_pooled[b*CC + tid];
    __syncthreads();
    {
        const float4* r1 = (const float4*)(fc1 + (size_t)tid * CC);
        float a = 0.f;
        #pragma unroll 8
        for (int j = 0; j < CC/4; j++) {
            float4 v = r1[j];
            a += ps[4*j]*v.x + ps[4*j+1]*v.y + ps[4*j+2]*v.z + ps[4*j+3]*v.w;
        }
        hs[tid] = fmaxf(a, 0.f);
    }
    __syncthreads();
    #pragma unroll
    for (int m4 = 0; m4 < 4; m4++) {
        int m = m4*CC + tid;                        // m = c*4 + t
        const float4* r2 = (const float4*)(fc2 + (size_t)m * CC);
        float s = fc2b[m];
        #pragma unroll 8
        for (int j = 0; j < CC/4; j++) {
            float4 v = r2[j];
            s += hs[4*j]*v.x + hs[4*j+1]*v.y + hs[4*j+2]*v.z + hs[4*j+3]*v.w;
        }
        g_kern[b*CC*4 + m] = s;
    }
}

// ---------------------------------------------------------------
// Kernel 3: fp16 A images. One thread per 16B quad (8 kk values; 9 per row).
//   row = (b*32 + s)*256 + o  (o = 0..255, og merged)
//   A[kk] = sigmoid(sum_t kern[b,c0+ci,t]*cog[o,t,r9]) * weight[o,c0+ci,r9]
//   kk = ci*9 + r9, ci 0..7. words 36..43 zeroed by g==0 thread.
// ---------------------------------------------------------------
__global__ void dynw_kernel(const float* __restrict__ cog,
                            const float* __restrict__ weight) {
    int idx = blockIdx.x * 256 + threadIdx.x;   // < 262144 * 9
    int row = idx / 9;
    int g   = idx - row * 9;                     // quad id: kk = g*8 .. g*8+7
    int o_g = row & 255;
    int s   = (row >> 8) & 31;
    int b   = row >> 13;
    int c0 = s*KCH;

    const float* cg = cog + (size_t)o_g * 36;
    const float4* wp = (const float4*)(weight + ((size_t)o_g*CC + c0)*9 + g*8);
    float4 wq0 = wp[0], wq1 = wp[1];
    float wv[8] = {wq0.x, wq0.y, wq0.z, wq0.w, wq1.x, wq1.y, wq1.z, wq1.w};
    float d[8];
    #pragma unroll
    for (int u = 0; u < 8; u++) {
        int kk = g*8 + u;
        int ci = kk/9, r9 = kk - ci*9;
        const float4 kv = *(const float4*)(g_kern + ((size_t)b*CC + c0 + ci)*4);
        float sa = kv.x*cg[r9] + kv.y*cg[9+r9] + kv.z*cg[18+r9] + kv.w*cg[27+r9];
        sa = fminf(fmaxf(sa, -15.f), 15.f);
        d[u] = 1.0f + fast_exp(-sa);
    }
    unsigned w[4];
    #pragma unroll
    for (int h4 = 0; h4 < 2; h4++) {
        float d0 = d[h4*4], d1 = d[h4*4+1], d2 = d[h4*4+2], d3 = d[h4*4+3];
        float p01 = d0*d1, p23 = d2*d3;
        float P = p01 * p23;
        float rp; asm("rcp.approx.f32 %0, %1;" : "=f"(rp) : "f"(P));
        float v0 = wv[h4*4+0] * (rp*d1*p23);
        float v1 = wv[h4*4+1] * (rp*d0*p23);
        float v2 = wv[h4*4+2] * (rp*p01*d3);
        float v3 = wv[h4*4+3] * (rp*p01*d2);
        w[h4*2+0] = h2bits(v0, v1);
        w[h4*2+1] = h2bits(v2, v3);
    }
    unsigned* dst = g_wA + (size_t)row * SWD + g*4;
    STG128(dst, w[0], w[1], w[2], w[3]);
    if (g == 0) {   // zero words 36..43 (kk 72..79 zero-k tail + pad)
        unsigned* z = g_wA + (size_t)row * SWD + 36;
        STG128(z, 0u, 0u, 0u, 0u);
        STG128(z + 4, 0u, 0u, 0u, 0u);
    }
}

// ---------------------------------------------------------------
// Kernel 4: FP16 mma.sync implicit-GEMM conv, og merged.
// Block (tile, b): D[256 o][112 px(2 rows x 56)]; stage = 8ch x 9taps
// (80 fp16 k, 5 ksteps of 16), 32 stages. Triple-buffered A (cp.async,
// wait_group 1), double-buffered B (LDG reg prefetch 20+16, STS commit
// interleaved). 8 warps = 4(M) x 2(N); warp tile 64 o x 56 px.
// ---------------------------------------------------------------
__global__ __launch_bounds__(256, 1)
void conv_kernel(const float* __restrict__ x, float* __restrict__ out) {
    extern __shared__ __align__(16) float dsm[];
    unsigned* As = (unsigned*)dsm;               // [3][A_WORDS]
    unsigned* Bs = (unsigned*)dsm + 3*A_WORDS;   // [2][B_WORDS]

    const int tid  = threadIdx.x;
    const int lane = tid & 31;
    const int wid  = tid >> 5;
    const int warpM = wid & 3;                   // 64-o slab
    const int warpN = wid >> 2;                  // 56-px slab (output row)
    const int tile = blockIdx.x, b = blockIdx.y;
    const int h0 = tile * 2;

    const float* xb = x + (size_t)b * CC * HWSZ;
    const uint4* gA = (const uint4*)g_wA + (size_t)(b * NST3) * A_CH;

    // ---- B feed mapping: half = tid/112 (kk base = half*36), px = tid%112 ----
    const int half = tid / 112;          // 0,1 active; 2 inactive
    const int px   = tid - half*112;
    const bool bact = (tid < 224);
    const int rr = px / 56, cw = px % 56;
    const int ghb = h0 + rr - 1, gwb = cw - 1;
    const int cbase = ghb*WW + gwb;

    unsigned vmask0 = 0, vmask1 = 0;
    {
        #pragma unroll
        for (int u = 0; u < 20; u++) {
            int kk = half*36 + u;
            int ci = kk/9, r9 = kk - ci*9;
            int i3 = r9/3, j3 = r9 - i3*3;
            int gh = ghb + i3, gw = gwb + j3;
            bool ok = bact && (gh >= 0) && (gh < HH) && (gw >= 0) && (gw < WW);
            vmask0 |= (ok ? 1u : 0u) << u;
        }
        #pragma unroll
        for (int u = 0; u < 16; u++) {
            int kk = half*36 + 20 + u;
            int ci = kk/9, r9 = kk - ci*9;
            int i3 = r9/3, j3 = r9 - i3*3;
            int gh = ghb + i3, gw = gwb + j3;
            bool ok = bact && (gh >= 0) && (gh < HH) && (gw >= 0) && (gw < WW);
            vmask1 |= (ok ? 1u : 0u) << u;
        }
    }

    float acc[4][7][4];
    #pragma unroll
    for (int m = 0; m < 4; m++)
        #pragma unroll
        for (int n = 0; n < 7; n++)
            #pragma unroll
            for (int q = 0; q < 4; q++) acc[m][n][q] = 0.f;

    // ---- ldmatrix lane-address offsets (bytes), row stride 176B ----
    const unsigned aoffL = (unsigned)((warpM*64 + (lane & 15))*ROWB + (lane >> 4)*16);
    const unsigned boffL = (unsigned)((warpN*56 + ((lane >> 4))*8 + (lane & 7))*ROWB
                                     + (((lane >> 3) & 1))*16);
    const unsigned boffL2 = (unsigned)((warpN*56 + 48 + (lane & 7))*ROWB
                                      + (((lane >> 3) & 1))*16);

    // compile-time offset prefetch; K0 is a literal
    #define PF_B20(XS, K0)                                                       \
        _Pragma("unroll")                                                        \
        for (int u_ = 0; u_ < 20; u_++) {                                        \
            const int kk_ = (K0) + u_;                                           \
            const int off_ = (kk_/9)*HWSZ + (((kk_%9))/3)*WW + ((kk_%9)%3);      \
            vreg[u_] = ((vmask0 >> u_) & 1) ? __ldg((XS) + cbase + off_) : 0.f;  \
        }
    #define PF_B16(XS, K0)                                                       \
        _Pragma("unroll")                                                        \
        for (int u_ = 0; u_ < 16; u_++) {                                        \
            const int kk_ = (K0) + u_;                                           \
            const int off_ = (kk_/9)*HWSZ + (((kk_%9))/3)*WW + ((kk_%9)%3);      \
            vreg[u_] = ((vmask1 >> u_) & 1) ? __ldg((XS) + cbase + off_) : 0.f;  \
        }

    #define ISSUE_A(S, BUF)                                                      \
    {                                                                            \
        const uint4* srcA_ = gA + (size_t)(S) * A_CH;                            \
        unsigned dA_ = smem_u32(As) + (unsigned)(BUF)*A_BYTES;                   \
        _Pragma("unroll")                                                        \
        for (int i_ = 0; i_ < 11; i_++) {                                        \
            int ch_ = tid + i_ * 256;                                            \
            cp_async16(dA_ + ch_*16, srcA_ + ch_);                               \
        }                                                                        \
        asm volatile("cp.async.commit_group;");                                  \
    }

    // pass0: 20 fp32 -> words (half*18 .. +9) of the row
    #define COMMIT_B0(BUF)                                                       \
    if (bact) {                                                                  \
        unsigned w_[10];                                                         \
        _Pragma("unroll")                                                        \
        for (int i_ = 0; i_ < 10; i_++)                                          \
            w_[i_] = h2bits(vreg[2*i_], vreg[2*i_+1]);                           \
        unsigned db_ = smem_u32(Bs) + (BUF)*B_BYTES + px*ROWB;                   \
        if (half == 0) {                                                         \
            STS128(db_ + 0,  w_[0], w_[1], w_[2], w_[3]);                        \
            STS128(db_ + 16, w_[4], w_[5], w_[6], w_[7]);                        \
            STS64 (db_ + 32, w_[8], w_[9]);                                      \
        } else {                                                                 \
            STS64 (db_ + 72, w_[0], w_[1]);                                      \
            STS128(db_ + 80, w_[2], w_[3], w_[4], w_[5]);                        \
            STS128(db_ + 96, w_[6], w_[7], w_[8], w_[9]);                        \
        }                                                                        \
    }
    // pass1: 16 fp32 -> words (half*18+10 .. +17)
    #define COMMIT_B1(BUF)                                                       \
    if (bact) {                                                                  \
        unsigned w_[8];                                                          \
        _Pragma("unroll")                                                        \
        for (int i_ = 0; i_ < 8; i_++)                                           \
            w_[i_] = h2bits(vreg[2*i_], vreg[2*i_+1]);                           \
        unsigned db_ = smem_u32(Bs) + (BUF)*B_BYTES + px*ROWB;                   \
        if (half == 0) {                                                         \
            STS64 (db_ + 40, w_[0], w_[1]);                                      \
            STS128(db_ + 48, w_[2], w_[3], w_[4], w_[5]);                        \
            STS64 (db_ + 64, w_[6], w_[7]);                                      \
        } else {                                                                 \
            STS128(db_ + 112, w_[0], w_[1], w_[2], w_[3]);                       \
            STS128(db_ + 128, w_[4], w_[5], w_[6], w_[7]);                       \
        }                                                                        \
    }

    #define MMA_KS(ks)                                                           \
    {                                                                            \
        unsigned af[4][4];                                                       \
        LDSM4(af[0][0], af[0][1], af[0][2], af[0][3], Ab + aoffL + (ks)*32);     \
        LDSM4(af[1][0], af[1][1], af[1][2], af[1][3], Ab + aoffL + 16*ROWB + (ks)*32); \
        LDSM4(af[2][0], af[2][1], af[2][2], af[2][3], Ab + aoffL + 32*ROWB + (ks)*32); \
        LDSM4(af[3][0], af[3][1], af[3][2], af[3][3], Ab + aoffL + 48*ROWB + (ks)*32); \
        {                                                                        \
            unsigned bf[4];                                                      \
            LDSM4(bf[0], bf[1], bf[2], bf[3], Bb + boffL + (ks)*32);             \
            _Pragma("unroll")                                                    \
            for (int m = 0; m < 4; m++) {                                        \
                MMA16(acc[m][0], af[m][0], af[m][1], af[m][2], af[m][3], bf[0], bf[1]); \
                MMA16(acc[m][1], af[m][0], af[m][1], af[m][2], af[m][3], bf[2], bf[3]); \
            }                                                                    \
        }                                                                        \
        {                                                                        \
            unsigned bf[4];                                                      \
            LDSM4(bf[0], bf[1], bf[2], bf[3], Bb + boffL + 16*ROWB + (ks)*32);   \
            _Pragma("unroll")                                                    \
            for (int m = 0; m < 4; m++) {                                        \
                MMA16(acc[m][2], af[m][0], af[m][1], af[m][2], af[m][3], bf[0], bf[1]); \
                MMA16(acc[m][3], af[m][0], af[m][1], af[m][2], af[m][3], bf[2], bf[3]); \
            }                                                                    \
        }                                                                        \
        {                                                                        \
            unsigned bf[4];                                                      \
            LDSM4(bf[0], bf[1], bf[2], bf[3], Bb + boffL + 32*ROWB + (ks)*32);   \
            _Pragma("unroll")                                                    \
            for (int m = 0; m < 4; m++) {                                        \
                MMA16(acc[m][4], af[m][0], af[m][1], af[m][2], af[m][3], bf[0], bf[1]); \
                MMA16(acc[m][5], af[m][0], af[m][1], af[m][2], af[m][3], bf[2], bf[3]); \
            }                                                                    \
        }                                                                        \
        {                                                                        \
            unsigned bf[2];                                                      \
            LDSM2(bf[0], bf[1], Bb + boffL2 + (ks)*32);                          \
            _Pragma("unroll")                                                    \
            for (int m = 0; m < 4; m++)                                          \
                MMA16(acc[m][6], af[m][0], af[m][1], af[m][2], af[m][3], bf[0], bf[1]); \
        }                                                                        \
    }

    // ---- zero B words 36..43 (kk 72..79 + pad) once, both buffers ----
    if (tid < 112) {
        STS128(smem_u32(Bs) + 0*B_BYTES + tid*ROWB + 144, 0u, 0u, 0u, 0u);
        STS128(smem_u32(Bs) + 0*B_BYTES + tid*ROWB + 160, 0u, 0u, 0u, 0u);
        STS128(smem_u32(Bs) + 1*B_BYTES + tid*ROWB + 144, 0u, 0u, 0u, 0u);
        STS128(smem_u32(Bs) + 1*B_BYTES + tid*ROWB + 160, 0u, 0u, 0u, 0u);
    }

    // ---- prologue: A(0)->buf0, A(1)->buf1, B(0)->Bbuf0 ----
    {
        float vreg[20];
        ISSUE_A(0, 0);
        ISSUE_A(1, 1);
        if (bact) {
            if (half == 0) { PF_B20(xb, 0)  } else { PF_B20(xb, 36) }
        }
        COMMIT_B0(0);
        if (bact) {
            if (half == 0) { PF_B16(xb, 20) } else { PF_B16(xb, 56) }
        }
        COMMIT_B1(0);
        asm volatile("cp.async.wait_group 1;");   // A(0) done; A(1) may be pending
        __syncthreads();
    }

    int pr = 0;   // A read buffer = s % 3
    for (int s = 0; s < NST3; s++) {
        const int q = s & 1;
        float vreg[20];

        // ---- issue A(s+2) ----
        if (s + 2 < NST3) {
            int pi = pr + 2; if (pi >= 3) pi -= 3;
            ISSUE_A(s + 2, pi);
        }
        const float* xs = xb + (size_t)(s + 1) * (KCH*HWSZ);
        // ---- B(s+1) pass0 prefetch ----
        if (s + 1 < NST3 && bact) {
            if (half == 0) { PF_B20(xs, 0) } else { PF_B20(xs, 36) }
        }

        const unsigned Ab = smem_u32(As) + (unsigned)pr*A_BYTES;
        const unsigned Bb = smem_u32(Bs) + (unsigned)q*B_BYTES;
        MMA_KS(0)
        MMA_KS(1)

        if (s + 1 < NST3) {
            COMMIT_B0(q ^ 1);
            if (bact) {
                if (half == 0) { PF_B16(xs, 20) } else { PF_B16(xs, 56) }
            }
        }

        MMA_KS(2)
        MMA_KS(3)
        MMA_KS(4)

        if (s + 1 < NST3) COMMIT_B1(q ^ 1);

        if (s + 2 < NST3) { asm volatile("cp.async.wait_group 1;"); }
        else              { asm volatile("cp.async.wait_group 0;"); }
        __syncthreads();
        pr++; if (pr == 3) pr = 0;
    }
    #undef ISSUE_A
    #undef COMMIT_B0
    #undef COMMIT_B1
    #undef PF_B20
    #undef PF_B16
    #undef MMA_KS

    // ---- epilogue: fragments -> gmem (all px of a warp share one h row) ----
    const int h = h0 + warpN;
    const int wbase = (lane & 3) * 2;
    #pragma unroll
    for (int m = 0; m < 4; m++) {
        int o = warpM*64 + m*16 + (lane >> 2);
        float* r0 = out + ((size_t)b*OO + o)*HWSZ + h*WW;
        float* r1 = out + ((size_t)b*OO + o + 8)*HWSZ + h*WW;
        #pragma unroll
        for (int n = 0; n < 7; n++) {
            int w = n*8 + wbase;
            *(float2*)(r0 + w) = make_float2(acc[m][n][0], acc[m][n][1]);
            *(float2*)(r1 + w) = make_float2(acc[m][n][2], acc[m][n][3]);
        }
    }
}

// ---------------------------------------------------------------
extern "C" void kernel_launch(void* const* d_in, const int* in_sizes, int n_in,
                              void* d_out, int out_size) {
    const float* x      = (const float*)d_in[0];
    const float* fc1_w  = (const float*)d_in[1];
    const float* fc2_w  = (const float*)d_in[2];
    const float* fc2_b  = (const float*)d_in[3];
    const float* cog_w  = (const float*)d_in[4];
    const float* weight = (const float*)d_in[5];
    float* out = (float*)d_out;

    cudaFuncSetAttribute(conv_kernel, cudaFuncAttributeMaxDynamicSharedMemorySize, SMEM_CONV);

    pool_kernel<<<BB*CC, 256>>>(x);
    fc_kernel<<<BB, 256>>>(fc1_w, fc2_w, fc2_b);
    dynw_kernel<<<9216, 256>>>(cog_w, weight);   // 262144 rows x 9 quads
    {
        dim3 grid(28, BB);
        conv_kernel<<<grid, 256, SMEM_CONV>>>(x, out);
    }
}